// round 13
// baseline (speedup 1.0000x reference)
#include <cuda_runtime.h>
#include <cuda_fp16.h>
#include <math.h>

#define BSZ 131072
#define CR  64
#define NTH 256
#define SA  264   // activation plane stride (half)
#define SW2 40    // fwd/bwd staged tile stride (32 k + 8 pad)
#define SV2 136   // Vw3 half-tile stride (128 + 8)

typedef unsigned int u32;
typedef unsigned short u16;

// ---------------- weight images (half) ----------------
__device__ __align__(16) u16 gVw2s[65536];
__device__ __align__(16) u16 gUw2s[65536];
__device__ __align__(16) u16 gVw3s[16384];

__global__ void prep_kernel(const float* __restrict__ Vw2,
                            const float* __restrict__ Vw3,
                            const float* __restrict__ Uw2) {
    int i = blockIdx.x * blockDim.x + threadIdx.x;
    if (i >= 147456) return;
    float v; u16* dst; int idx;
    if (i < 65536)       { idx = i;          v = Vw2[idx]; dst = gVw2s; }
    else if (i < 131072) { idx = i - 65536;  v = Uw2[idx]; dst = gUw2s; }
    else                 { idx = i - 131072; v = Vw3[idx]; dst = gVw3s; }
    dst[idx] = __half_as_ushort(__float2half_rn(v));
}

// ---------------- smem (~104KB -> 2 CTAs/SM) ----------------
struct Smem {
    u16 AH[CR * SA], AL[CR * SA];   // activation planes hi/lo
    u16 WH[10240];                  // staged weight tile (256*40 or 64*136)
    float X[CR][4];
    float Vw1s[256][4], Uw1s[256][4];
    float Vb1s[256], Vb2s[256], Ub1s[256], Ub2s[256], Uw3s[256];
    float Vb3s[64];
    float Vpart[CR];
    float Upart[CR][4];
    float Gpart[CR][2][4];
};

// ---------------- helpers ----------------
__device__ __forceinline__ u32 s2u(const void* p) {
    u32 a; asm("{ .reg .u64 t; cvta.to.shared.u64 t, %1; cvt.u32.u64 %0, t; }"
               : "=r"(a) : "l"(p));
    return a;
}
__device__ __forceinline__ void ldsm4(u32& r0, u32& r1, u32& r2, u32& r3, u32 a) {
    asm volatile("ldmatrix.sync.aligned.m8n8.x4.shared.b16 {%0,%1,%2,%3}, [%4];"
                 : "=r"(r0), "=r"(r1), "=r"(r2), "=r"(r3) : "r"(a));
}
__device__ __forceinline__ void ldsm4t(u32& r0, u32& r1, u32& r2, u32& r3, u32 a) {
    asm volatile("ldmatrix.sync.aligned.m8n8.x4.trans.shared.b16 {%0,%1,%2,%3}, [%4];"
                 : "=r"(r0), "=r"(r1), "=r"(r2), "=r"(r3) : "r"(a));
}
__device__ __forceinline__ void mma4(float* c, u32 a0, u32 a1, u32 a2, u32 a3,
                                     u32 b0, u32 b1) {
    asm volatile("mma.sync.aligned.m16n8k16.row.col.f32.f16.f16.f32 "
                 "{%0,%1,%2,%3}, {%4,%5,%6,%7}, {%8,%9}, {%0,%1,%2,%3};"
                 : "+f"(c[0]), "+f"(c[1]), "+f"(c[2]), "+f"(c[3])
                 : "r"(a0), "r"(a1), "r"(a2), "r"(a3), "r"(b0), "r"(b1));
}
__device__ __forceinline__ void packp(float a, float b, u32& h, u32& l) {
    __half h0 = __float2half_rn(a), h1 = __float2half_rn(b);
    float r0 = a - __half2float(h0), r1 = b - __half2float(h1);
    h = (u32)__half_as_ushort(h0) | ((u32)__half_as_ushort(h1) << 16);
    l = (u32)__half_as_ushort(__float2half_rn(r0)) |
        ((u32)__half_as_ushort(__float2half_rn(r1)) << 16);
}
__device__ __forceinline__ float hlo(u32 v) {
    return __half2float(__ushort_as_half((u16)(v & 0xFFFF)));
}
__device__ __forceinline__ float hhi(u32 v) {
    return __half2float(__ushort_as_half((u16)(v >> 16)));
}

// stage 256 rows x 32 k-cols (k offset s*32) at stride SW2
__device__ __forceinline__ void stageW32(const u16* gw, u16* WH, int s, int tid) {
    #pragma unroll 1
    for (int i = tid; i < 1024; i += NTH) {
        int row = i >> 2, u = i & 3;
        *(uint4*)&WH[row * SW2 + u * 8] =
            *(const uint4*)&gw[row * 256 + (s << 5) + u * 8];
    }
}
// stage 64 rows x 128 k-cols (k offset ks*128) at stride SV2
__device__ __forceinline__ void stageV32(const u16* gw, u16* WH, int ks, int tid) {
    #pragma unroll 1
    for (int i = tid; i < 1088; i += NTH) {
        int row = i / 17, u = i % 17;
        *(uint4*)&WH[row * SV2 + u * 8] =
            *(const uint4*)&gw[row * 256 + (ks << 7) + u * 8];
    }
}

// K=256, N=256 forward GEMM: warp = 32 M-rows (2 sub) x 64 N (nq quarter)
__device__ __forceinline__ void fwd256h(const u16* gw, float* acc, Smem& S,
                                        u32 smAH, u32 smAL, u32 smWH,
                                        int tid, int lane, int nq, int R0) {
    u32 aoff = ((u32)((lane & 15) * SA + 8 * (lane >> 4))) * 2;
    int m = lane >> 3;
    u32 boff = ((u32)(((lane & 7) + 8 * (m >> 1)) * SW2 + 8 * (m & 1))) * 2;
    u32 aHb = smAH + (u32)(R0 * SA) * 2 + aoff;
    u32 aLb = smAL + (u32)(R0 * SA) * 2 + aoff;
    #pragma unroll 1
    for (int s = 0; s < 8; s++) {
        __syncthreads();
        stageW32(gw, S.WH, s, tid);
        __syncthreads();
        #pragma unroll
        for (int q = 0; q < 2; q++) {
            int k = (s << 5) + (q << 4);
            u32 ah[2][4], al[2][4];
            #pragma unroll
            for (int sub = 0; sub < 2; sub++) {
                u32 sof = (u32)(sub * 16 * SA + k) * 2;
                ldsm4(ah[sub][0], ah[sub][1], ah[sub][2], ah[sub][3], aHb + sof);
                ldsm4(al[sub][0], al[sub][1], al[sub][2], al[sub][3], aLb + sof);
            }
            #pragma unroll
            for (int fp = 0; fp < 4; fp++) {
                int n0 = (nq << 6) + (fp << 4);
                u32 bb = (u32)(n0 * SW2 + (q << 4)) * 2;
                u32 b0, b1, b2, b3;
                ldsm4(b0, b1, b2, b3, smWH + boff + bb);
                #pragma unroll
                for (int sub = 0; sub < 2; sub++) {
                    float* c = acc + (((sub << 2) + fp) << 3);
                    mma4(c, ah[sub][0], ah[sub][1], ah[sub][2], ah[sub][3], b0, b1);
                    mma4(c, al[sub][0], al[sub][1], al[sub][2], al[sub][3], b0, b1);
                    mma4(c + 4, ah[sub][0], ah[sub][1], ah[sub][2], ah[sub][3], b2, b3);
                    mma4(c + 4, al[sub][0], al[sub][1], al[sub][2], al[sub][3], b2, b3);
                }
            }
        }
    }
}

// layer-1: tanh(x @ W1^T + b) into half planes; thread: 1 row x 64 cols
__device__ __forceinline__ void layer1w(Smem& S, const float (*W)[4],
                                        const float* bv, int tid) {
    int row = tid >> 2, cb = (tid & 3) << 6;
    float x0 = S.X[row][0], x1 = S.X[row][1], x2 = S.X[row][2], x3 = S.X[row][3];
    #pragma unroll 4
    for (int j = 0; j < 32; j++) {
        int col = cb + (j << 1);
        const float* w0 = W[col];
        const float* w1 = W[col + 1];
        float z0 = fmaf(x0, w0[0], fmaf(x1, w0[1], fmaf(x2, w0[2], fmaf(x3, w0[3], bv[col]))));
        float z1 = fmaf(x0, w1[0], fmaf(x1, w1[1], fmaf(x2, w1[2], fmaf(x3, w1[3], bv[col + 1]))));
        u32 h, l;
        packp(tanhf(z0), tanhf(z1), h, l);
        *(u32*)&S.AH[row * SA + col] = h;
        *(u32*)&S.AL[row * SA + col] = l;
    }
}

__global__ void __launch_bounds__(NTH, 2)
clf_mma(const float* __restrict__ x,
        const float* __restrict__ Vw1, const float* __restrict__ Vb1,
        const float* __restrict__ Vb2, const float* __restrict__ Vb3,
        const float* __restrict__ Uw1, const float* __restrict__ Ub1,
        const float* __restrict__ Ub2, const float* __restrict__ Uw3,
        const float* __restrict__ Ub3, float* __restrict__ out) {
    extern __shared__ char smraw[];
    Smem& S = *reinterpret_cast<Smem*>(smraw);
    const int tid = threadIdx.x, lane = tid & 31, wid = tid >> 5;
    // big-GEMM mapping: 2 M-tiles(32) x 4 N-quarters
    const int nq = wid & 3, R0n = (wid >> 2) << 5;
    // small-GEMM mapping: 4 M-tiles(16) x 2 N-halves
    const int nh = wid & 1, R0o = (wid >> 1) << 4;
    const int r4 = lane >> 2, c2 = (lane & 3) << 1, m = lane >> 3;
    const int rowAo = R0o + r4, rowBo = rowAo + 8;
    const int base = blockIdx.x * CR;

    // ---- parameter staging ----
    for (int i = tid; i < CR * 4; i += NTH) S.X[i >> 2][i & 3] = x[base * 4 + i];
    for (int i = tid; i < 1024; i += NTH) {
        ((float*)S.Vw1s)[i] = Vw1[i];
        ((float*)S.Uw1s)[i] = Uw1[i];
    }
    for (int i = tid; i < 256; i += NTH) {
        S.Vb1s[i] = Vb1[i]; S.Vb2s[i] = Vb2[i];
        S.Ub1s[i] = Ub1[i]; S.Ub2s[i] = Ub2[i]; S.Uw3s[i] = Uw3[i];
    }
    for (int i = tid; i < 64; i += NTH) S.Vb3s[i] = Vb3[i];
    __syncthreads();

    const u32 smAH = s2u(S.AH), smAL = s2u(S.AL), smWH = s2u(S.WH);

    // ---- a1 planes ----
    layer1w(S, S.Vw1s, S.Vb1s, tid);

    // ==== G1: a2 = tanh(a1 @ Vw2^T + b2) ====
    {
        float acc[64];
        #pragma unroll
        for (int i = 0; i < 64; i++) acc[i] = 0.f;
        fwd256h(gVw2s, acc, S, smAH, smAL, smWH, tid, lane, nq, R0n);
        __syncthreads();  // all a1-plane reads done before overwrite
        #pragma unroll
        for (int sub = 0; sub < 2; sub++) {
            int rA = R0n + (sub << 4) + r4, rB = rA + 8;
            #pragma unroll
            for (int fp = 0; fp < 4; fp++) {
                float* c = acc + (((sub << 2) + fp) << 3);
                #pragma unroll
                for (int h2 = 0; h2 < 2; h2++) {
                    int n = (nq << 6) + (fp << 4) + (h2 << 3) + c2;
                    u32 h, l;
                    packp(tanhf(c[h2 * 4 + 0] + S.Vb2s[n]),
                          tanhf(c[h2 * 4 + 1] + S.Vb2s[n + 1]), h, l);
                    *(u32*)&S.AH[rA * SA + n] = h;
                    *(u32*)&S.AL[rA * SA + n] = l;
                    packp(tanhf(c[h2 * 4 + 2] + S.Vb2s[n]),
                          tanhf(c[h2 * 4 + 3] + S.Vb2s[n + 1]), h, l);
                    *(u32*)&S.AH[rB * SA + n] = h;
                    *(u32*)&S.AL[rB * SA + n] = l;
                }
            }
        }
    }

    // ==== G2: a3 = tanh(a2 @ Vw3^T + b3); V; w3 frags ====
    u32 w3h[16], w3l[16];
    {
        float a3c[32];
        #pragma unroll
        for (int i = 0; i < 32; i++) a3c[i] = 0.f;
        u32 aoff = ((u32)((lane & 15) * SA + 8 * (lane >> 4))) * 2;
        u32 aHb = smAH + (u32)(R0o * SA) * 2 + aoff;
        u32 aLb = smAL + (u32)(R0o * SA) * 2 + aoff;
        u32 boff3 = ((u32)(((lane & 7) + 8 * (m >> 1)) * SV2 + 8 * (m & 1))) * 2;
        #pragma unroll 1
        for (int ks = 0; ks < 2; ks++) {
            __syncthreads();
            stageV32(gVw3s, S.WH, ks, tid);
            __syncthreads();
            #pragma unroll 1
            for (int q = 0; q < 8; q++) {
                u32 ah0, ah1, ah2, ah3, al0, al1, al2, al3;
                ldsm4(ah0, ah1, ah2, ah3, aHb + (u32)(((ks << 3) + q) << 5));
                ldsm4(al0, al1, al2, al3, aLb + (u32)(((ks << 3) + q) << 5));
                #pragma unroll
                for (int fp = 0; fp < 4; fp++) {
                    u32 bb = (u32)((fp << 4) * SV2 + (q << 4)) * 2;
                    u32 b0, b1, b2, b3;
                    ldsm4(b0, b1, b2, b3, smWH + boff3 + bb);
                    float* c = a3c + (fp << 3);
                    mma4(c, ah0, ah1, ah2, ah3, b0, b1);
                    mma4(c, al0, al1, al2, al3, b0, b1);
                    mma4(c + 4, ah0, ah1, ah2, ah3, b2, b3);
                    mma4(c + 4, al0, al1, al2, al3, b2, b3);
                }
            }
        }
        float pvA = 0.f, pvB = 0.f;
        #pragma unroll
        for (int f = 0; f < 8; f++) {
            int n = (f << 3) + c2;
            float* c = a3c + ((f >> 1) << 3) + ((f & 1) << 2);
            float v0 = tanhf(c[0] + S.Vb3s[n]);
            float v1 = tanhf(c[1] + S.Vb3s[n + 1]);
            float v2 = tanhf(c[2] + S.Vb3s[n]);
            float v3 = tanhf(c[3] + S.Vb3s[n + 1]);
            pvA += v0 * v0 + v1 * v1;
            pvB += v2 * v2 + v3 * v3;
            int bidx = ((f >> 1) << 2) + ((f & 1) << 1);
            packp(v0 * (1.f - v0 * v0), v1 * (1.f - v1 * v1), w3h[bidx], w3l[bidx]);
            packp(v2 * (1.f - v2 * v2), v3 * (1.f - v3 * v3), w3h[bidx + 1], w3l[bidx + 1]);
        }
        pvA += __shfl_xor_sync(0xffffffffu, pvA, 1);
        pvA += __shfl_xor_sync(0xffffffffu, pvA, 2);
        pvB += __shfl_xor_sync(0xffffffffu, pvB, 1);
        pvB += __shfl_xor_sync(0xffffffffu, pvB, 2);
        if ((lane & 3) == 0 && nh == 0) {
            S.Vpart[rowAo] = pvA;
            S.Vpart[rowBo] = pvB;
        }
    }

    // ==== G3: t2' = (w3 @ Vw3) * (1 - a2^2), planes overwritten ====
    {
        float t2c[64];
        #pragma unroll
        for (int i = 0; i < 64; i++) t2c[i] = 0.f;
        u32 boffB3 = ((u32)(((lane & 7) + 8 * (m & 1)) * SV2 + 8 * (m >> 1))) * 2;
        #pragma unroll 1
        for (int ks = 0; ks < 2; ks++) {
            __syncthreads();
            stageV32(gVw3s, S.WH, ks, tid);
            __syncthreads();
            #pragma unroll
            for (int q = 0; q < 4; q++) {
                int a0 = q << 2;
                #pragma unroll
                for (int fp = 0; fp < 4; fp++) {
                    u32 bb = (u32)((q << 4) * SV2 + (nh << 6) + (fp << 4)) * 2;
                    u32 b0, b1, b2, b3;
                    ldsm4t(b0, b1, b2, b3, smWH + boffB3 + bb);
                    float* c = t2c + (((ks << 2) + fp) << 3);
                    mma4(c, w3h[a0], w3h[a0 + 1], w3h[a0 + 2], w3h[a0 + 3], b0, b1);
                    mma4(c, w3l[a0], w3l[a0 + 1], w3l[a0 + 2], w3l[a0 + 3], b0, b1);
                    mma4(c + 4, w3h[a0], w3h[a0 + 1], w3h[a0 + 2], w3h[a0 + 3], b2, b3);
                    mma4(c + 4, w3l[a0], w3l[a0 + 1], w3l[a0 + 2], w3l[a0 + 3], b2, b3);
                }
            }
        }
        // mask from a2 planes
        #pragma unroll
        for (int fr = 0; fr < 8; fr++) {
            int ks = fr >> 2, fp = fr & 3;
            #pragma unroll
            for (int h2 = 0; h2 < 2; h2++) {
                int n = (ks << 7) + (nh << 6) + (fp << 4) + (h2 << 3) + c2;
                float* c = t2c + (fr << 3) + (h2 << 2);
                u32 hA = *(u32*)&S.AH[rowAo * SA + n];
                u32 lA = *(u32*)&S.AL[rowAo * SA + n];
                u32 hB = *(u32*)&S.AH[rowBo * SA + n];
                u32 lB = *(u32*)&S.AL[rowBo * SA + n];
                float ax = hlo(hA) + hlo(lA), ay = hhi(hA) + hhi(lA);
                float bx = hlo(hB) + hlo(lB), by = hhi(hB) + hhi(lB);
                c[0] *= (1.f - ax * ax);
                c[1] *= (1.f - ay * ay);
                c[2] *= (1.f - bx * bx);
                c[3] *= (1.f - by * by);
            }
        }
        __syncthreads();
        #pragma unroll
        for (int fr = 0; fr < 8; fr++) {
            int ks = fr >> 2, fp = fr & 3;
            #pragma unroll
            for (int h2 = 0; h2 < 2; h2++) {
                int n = (ks << 7) + (nh << 6) + (fp << 4) + (h2 << 3) + c2;
                float* c = t2c + (fr << 3) + (h2 << 2);
                u32 h, l;
                packp(c[0], c[1], h, l);
                *(u32*)&S.AH[rowAo * SA + n] = h;
                *(u32*)&S.AL[rowAo * SA + n] = l;
                packp(c[2], c[3], h, l);
                *(u32*)&S.AH[rowBo * SA + n] = h;
                *(u32*)&S.AL[rowBo * SA + n] = l;
            }
        }
    }

    // ==== G4: t1' = (t2' @ Vw2)*(1-a1^2); grad_V = t1' @ Vw1 ====
    float gpA[4] = {0.f, 0.f, 0.f, 0.f}, gpB[4] = {0.f, 0.f, 0.f, 0.f};
    {
        float xa0 = S.X[rowAo][0], xa1 = S.X[rowAo][1], xa2 = S.X[rowAo][2], xa3 = S.X[rowAo][3];
        float xb0 = S.X[rowBo][0], xb1 = S.X[rowBo][1], xb2 = S.X[rowBo][2], xb3 = S.X[rowBo][3];
        u32 aoff = ((u32)((lane & 15) * SA + 8 * (lane >> 4))) * 2;
        u32 aHb = smAH + (u32)(R0o * SA) * 2 + aoff;
        u32 aLb = smAL + (u32)(R0o * SA) * 2 + aoff;
        u32 boffB = ((u32)(((lane & 7) + 8 * (m & 1)) * SW2 + 8 * (m >> 1))) * 2;
        #pragma unroll 1
        for (int s = 0; s < 8; s++) {
            __syncthreads();
            stageW32(gVw2s, S.WH, s, tid);
            __syncthreads();
            float c8[8];
            #pragma unroll
            for (int i = 0; i < 8; i++) c8[i] = 0.f;
            #pragma unroll 1
            for (int q = 0; q < 16; q++) {
                u32 ah0, ah1, ah2, ah3, al0, al1, al2, al3;
                ldsm4(ah0, ah1, ah2, ah3, aHb + (u32)(q << 5));
                ldsm4(al0, al1, al2, al3, aLb + (u32)(q << 5));
                u32 bb = (u32)((q << 4) * SW2 + (nh << 4)) * 2;
                u32 b0, b1, b2, b3;
                ldsm4t(b0, b1, b2, b3, smWH + boffB + bb);
                mma4(c8, ah0, ah1, ah2, ah3, b0, b1);
                mma4(c8, al0, al1, al2, al3, b0, b1);
                mma4(c8 + 4, ah0, ah1, ah2, ah3, b2, b3);
                mma4(c8 + 4, al0, al1, al2, al3, b2, b3);
            }
            #pragma unroll
            for (int f = 0; f < 2; f++) {
                int n = (s << 5) + (nh << 4) + (f << 3) + c2;
                float* c = c8 + (f << 2);
                #pragma unroll
                for (int e = 0; e < 4; e++) {
                    int nn = n + (e & 1);
                    const float* w = S.Vw1s[nn];
                    float z;
                    if (e < 2)
                        z = fmaf(xa0, w[0], fmaf(xa1, w[1], fmaf(xa2, w[2], fmaf(xa3, w[3], S.Vb1s[nn]))));
                    else
                        z = fmaf(xb0, w[0], fmaf(xb1, w[1], fmaf(xb2, w[2], fmaf(xb3, w[3], S.Vb1s[nn]))));
                    float a1v = tanhf(z);
                    float t = c[e] * (1.f - a1v * a1v);
                    float* gp = (e < 2) ? gpA : gpB;
                    gp[0] = fmaf(t, w[0], gp[0]);
                    gp[1] = fmaf(t, w[1], gp[1]);
                    gp[2] = fmaf(t, w[2], gp[2]);
                    gp[3] = fmaf(t, w[3], gp[3]);
                }
            }
        }
        #pragma unroll
        for (int j = 0; j < 4; j++) {
            gpA[j] += __shfl_xor_sync(0xffffffffu, gpA[j], 1);
            gpA[j] += __shfl_xor_sync(0xffffffffu, gpA[j], 2);
            gpB[j] += __shfl_xor_sync(0xffffffffu, gpB[j], 1);
            gpB[j] += __shfl_xor_sync(0xffffffffu, gpB[j], 2);
        }
        if ((lane & 3) == 0) {
            #pragma unroll
            for (int j = 0; j < 4; j++) {
                S.Gpart[rowAo][nh][j] = gpA[j];
                S.Gpart[rowBo][nh][j] = gpB[j];
            }
        }
    }

    // ==== G5: u1 planes + u2 GEMM + fold dot(Uw3) ====
    __syncthreads();
    layer1w(S, S.Uw1s, S.Ub1s, tid);
    {
        float acc[64];
        #pragma unroll
        for (int i = 0; i < 64; i++) acc[i] = 0.f;
        fwd256h(gUw2s, acc, S, smAH, smAL, smWH, tid, lane, nq, R0n);
        float pu[2][2] = {{0.f, 0.f}, {0.f, 0.f}};
        #pragma unroll
        for (int sub = 0; sub < 2; sub++) {
            #pragma unroll
            for (int fp = 0; fp < 4; fp++) {
                float* c = acc + (((sub << 2) + fp) << 3);
                #pragma unroll
                for (int h2 = 0; h2 < 2; h2++) {
                    int n = (nq << 6) + (fp << 4) + (h2 << 3) + c2;
                    pu[sub][0] = fmaf(tanhf(c[h2 * 4 + 0] + S.Ub2s[n]), S.Uw3s[n], pu[sub][0]);
                    pu[sub][0] = fmaf(tanhf(c[h2 * 4 + 1] + S.Ub2s[n + 1]), S.Uw3s[n + 1], pu[sub][0]);
                    pu[sub][1] = fmaf(tanhf(c[h2 * 4 + 2] + S.Ub2s[n]), S.Uw3s[n], pu[sub][1]);
                    pu[sub][1] = fmaf(tanhf(c[h2 * 4 + 3] + S.Ub2s[n + 1]), S.Uw3s[n + 1], pu[sub][1]);
                }
            }
            pu[sub][0] += __shfl_xor_sync(0xffffffffu, pu[sub][0], 1);
            pu[sub][0] += __shfl_xor_sync(0xffffffffu, pu[sub][0], 2);
            pu[sub][1] += __shfl_xor_sync(0xffffffffu, pu[sub][1], 1);
            pu[sub][1] += __shfl_xor_sync(0xffffffffu, pu[sub][1], 2);
            if ((lane & 3) == 0) {
                S.Upart[R0n + (sub << 4) + r4][nq] = pu[sub][0];
                S.Upart[R0n + (sub << 4) + r4 + 8][nq] = pu[sub][1];
            }
        }
    }
    __syncthreads();

    // ==== final per-row epilogue ====
    if (tid < CR) {
        int b = tid;
        float V = 0.5f * S.Vpart[b];
        float uu = S.Upart[b][0] + S.Upart[b][1] + S.Upart[b][2] + S.Upart[b][3];
        float u = 20.f * tanhf(uu + Ub3[0]);
        float gv0 = S.Gpart[b][0][0] + S.Gpart[b][1][0];
        float gv1 = S.Gpart[b][0][1] + S.Gpart[b][1][1];
        float gv2 = S.Gpart[b][0][2] + S.Gpart[b][1][2];
        float gv3 = S.Gpart[b][0][3] + S.Gpart[b][1][3];
        float th = S.X[b][1], v = S.X[b][2], om = S.X[b][3];
        float s, c;
        sincosf(th, &s, &c);
        float den1 = c - 24.7f, den2 = c * c - 24.7f;
        float f2 = (c * (9.8f * s + 11.5f * v) + 68.4f * v - 1.2f * om * om * s) / den1;
        float f3 = (-58.8f * v * c - 243.5f * v - s * (208.3f + om * om * c)) / den2;
        float g2 = (-1.8f * c - 10.9f) / den1;
        float g3 = (9.3f * c + 38.6f) / den2;
        float Lf = gv0 * v + gv1 * om + gv2 * f2 + gv3 * f3;
        float Lg = gv2 * g2 + gv3 * g3;
        int r = base + b;
        out[r] = u;
        out[BSZ + r] = V;
        out[2 * BSZ + r] = Lf + Lg * u;
    }
}

extern "C" void kernel_launch(void* const* d_in, const int* in_sizes, int n_in,
                              void* d_out, int out_size) {
    const float* x   = (const float*)d_in[0];
    const float* Vw1 = (const float*)d_in[1];
    const float* Vb1 = (const float*)d_in[2];
    const float* Vw2 = (const float*)d_in[3];
    const float* Vb2 = (const float*)d_in[4];
    const float* Vw3 = (const float*)d_in[5];
    const float* Vb3 = (const float*)d_in[6];
    const float* Uw1 = (const float*)d_in[7];
    const float* Ub1 = (const float*)d_in[8];
    const float* Uw2 = (const float*)d_in[9];
    const float* Ub2 = (const float*)d_in[10];
    const float* Uw3 = (const float*)d_in[11];
    const float* Ub3 = (const float*)d_in[12];
    float* out = (float*)d_out;

    prep_kernel<<<288, 512>>>(Vw2, Vw3, Uw2);
    cudaFuncSetAttribute(clf_mma, cudaFuncAttributeMaxDynamicSharedMemorySize,
                         (int)sizeof(Smem));
    clf_mma<<<BSZ / CR, NTH, sizeof(Smem)>>>(
        x, Vw1, Vb1, Vb2, Vb3, Uw1, Ub1, Ub2, Uw3, Ub3, out);
}

// round 14
// speedup vs baseline: 1.1701x; 1.1701x over previous
#include <cuda_runtime.h>
#include <cuda_fp16.h>
#include <math.h>

#define BSZ 131072
#define CR  128
#define NTH 512
#define SA  264   // activation plane stride (half)
#define SWP 40    // pipelined staged tile stride (32 k + 8 pad)
#define SV3 264   // Vw3 full-tile stride
#define BUFB 20480  // bytes per staging buffer (256*40*2)

typedef unsigned int u32;
typedef unsigned short u16;

// ---------------- weight images (half) ----------------
__device__ __align__(16) u16 gVw2s[65536];
__device__ __align__(16) u16 gUw2s[65536];
__device__ __align__(16) u16 gVw3s[16384];

__global__ void prep_kernel(const float* __restrict__ Vw2,
                            const float* __restrict__ Vw3,
                            const float* __restrict__ Uw2) {
    int i = blockIdx.x * blockDim.x + threadIdx.x;
    if (i >= 147456) return;
    float v; u16* dst; int idx;
    if (i < 65536)       { idx = i;          v = Vw2[idx]; dst = gVw2s; }
    else if (i < 131072) { idx = i - 65536;  v = Uw2[idx]; dst = gUw2s; }
    else                 { idx = i - 131072; v = Vw3[idx]; dst = gVw3s; }
    dst[idx] = __half_as_ushort(__float2half_rn(v));
}

// ---------------- smem (~194KB, 1 CTA/SM) ----------------
struct Smem {
    u16 AH[CR * SA], AL[CR * SA];   // activation planes hi/lo
    u16 WH[20480];                  // double staging buffer / Vw3 full tile
    float X[CR][4];
    float Vw1s[256][4], Uw1s[256][4];
    float Vb1s[256], Vb2s[256], Ub1s[256], Ub2s[256], Uw3s[256];
    float Vb3s[64];
    float Vpart[CR];
    float Upart[CR][4];
    float Gpart[CR][2][4];
};

// ---------------- helpers ----------------
__device__ __forceinline__ u32 s2u(const void* p) {
    u32 a; asm("{ .reg .u64 t; cvta.to.shared.u64 t, %1; cvt.u32.u64 %0, t; }"
               : "=r"(a) : "l"(p));
    return a;
}
#define CPCOMMIT() asm volatile("cp.async.commit_group;" ::: "memory")
#define CPWAIT0()  asm volatile("cp.async.wait_group 0;" ::: "memory")
__device__ __forceinline__ void cp16(u32 dsm, const void* src) {
    asm volatile("cp.async.cg.shared.global [%0], [%1], 16;"
                 :: "r"(dsm), "l"(src) : "memory");
}
__device__ __forceinline__ void ldsm4(u32& r0, u32& r1, u32& r2, u32& r3, u32 a) {
    asm volatile("ldmatrix.sync.aligned.m8n8.x4.shared.b16 {%0,%1,%2,%3}, [%4];"
                 : "=r"(r0), "=r"(r1), "=r"(r2), "=r"(r3) : "r"(a));
}
__device__ __forceinline__ void ldsm4t(u32& r0, u32& r1, u32& r2, u32& r3, u32 a) {
    asm volatile("ldmatrix.sync.aligned.m8n8.x4.trans.shared.b16 {%0,%1,%2,%3}, [%4];"
                 : "=r"(r0), "=r"(r1), "=r"(r2), "=r"(r3) : "r"(a));
}
__device__ __forceinline__ void mma4(float* c, u32 a0, u32 a1, u32 a2, u32 a3,
                                     u32 b0, u32 b1) {
    asm volatile("mma.sync.aligned.m16n8k16.row.col.f32.f16.f16.f32 "
                 "{%0,%1,%2,%3}, {%4,%5,%6,%7}, {%8,%9}, {%0,%1,%2,%3};"
                 : "+f"(c[0]), "+f"(c[1]), "+f"(c[2]), "+f"(c[3])
                 : "r"(a0), "r"(a1), "r"(a2), "r"(a3), "r"(b0), "r"(b1));
}
__device__ __forceinline__ void packp(float a, float b, u32& h, u32& l) {
    __half h0 = __float2half_rn(a), h1 = __float2half_rn(b);
    float r0 = a - __half2float(h0), r1 = b - __half2float(h1);
    h = (u32)__half_as_ushort(h0) | ((u32)__half_as_ushort(h1) << 16);
    l = (u32)__half_as_ushort(__float2half_rn(r0)) |
        ((u32)__half_as_ushort(__float2half_rn(r1)) << 16);
}
__device__ __forceinline__ float hlo(u32 v) {
    return __half2float(__ushort_as_half((u16)(v & 0xFFFF)));
}
__device__ __forceinline__ float hhi(u32 v) {
    return __half2float(__ushort_as_half((u16)(v >> 16)));
}

// async stage: 256 rows x 32 k-cols (k offset s*32), stride SWP
__device__ __forceinline__ void stageA32(const u16* gw, u32 dsm, int s, int tid) {
    #pragma unroll
    for (int i = tid; i < 1024; i += NTH) {
        int row = i >> 2, u = i & 3;
        cp16(dsm + (u32)(row * SWP + u * 8) * 2,
             gw + row * 256 + (s << 5) + u * 8);
    }
}
// async stage Vw3 full: 64 rows x 256 k-cols, stride SV3
__device__ __forceinline__ void stageV3A(const u16* gw, u32 dsm, int tid) {
    #pragma unroll
    for (int i = tid; i < 2048; i += NTH) {
        int row = i >> 5, u = i & 31;
        cp16(dsm + (u32)(row * SV3 + u * 8) * 2,
             gw + row * 256 + u * 8);
    }
}

// K=256/N=256 forward GEMM, pipelined 8x32k stages.
// warp = 32 M-rows (2 sub) x 64 N (quarter nq)
__device__ __forceinline__ void fwd256h(const u16* gw, float* acc,
                                        u32 smAH, u32 smAL, u32 smWH,
                                        int tid, int lane, int nq, int R0) {
    u32 aoff = ((u32)((lane & 15) * SA + 8 * (lane >> 4))) * 2;
    int m = lane >> 3;
    u32 boff = ((u32)(((lane & 7) + 8 * (m >> 1)) * SWP + 8 * (m & 1))) * 2;
    u32 aHb = smAH + (u32)(R0 * SA) * 2 + aoff;
    u32 aLb = smAL + (u32)(R0 * SA) * 2 + aoff;
    stageA32(gw, smWH, 0, tid); CPCOMMIT();
    #pragma unroll 1
    for (int s = 0; s < 8; s++) {
        CPWAIT0();
        __syncthreads();
        if (s < 7) { stageA32(gw, smWH + ((s + 1) & 1) * BUFB, s + 1, tid); CPCOMMIT(); }
        u32 wb = smWH + (s & 1) * BUFB;
        #pragma unroll
        for (int q = 0; q < 2; q++) {
            int k = (s << 5) + (q << 4);
            u32 ah[2][4], al[2][4];
            #pragma unroll
            for (int sub = 0; sub < 2; sub++) {
                u32 sof = (u32)(sub * 16 * SA + k) * 2;
                ldsm4(ah[sub][0], ah[sub][1], ah[sub][2], ah[sub][3], aHb + sof);
                ldsm4(al[sub][0], al[sub][1], al[sub][2], al[sub][3], aLb + sof);
            }
            #pragma unroll
            for (int fp = 0; fp < 4; fp++) {
                int n0 = (nq << 6) + (fp << 4);
                u32 bb = (u32)(n0 * SWP + (q << 4)) * 2;
                u32 b0, b1, b2, b3;
                ldsm4(b0, b1, b2, b3, wb + boff + bb);
                #pragma unroll
                for (int sub = 0; sub < 2; sub++) {
                    float* c = acc + (((sub << 2) + fp) << 3);
                    mma4(c, ah[sub][0], ah[sub][1], ah[sub][2], ah[sub][3], b0, b1);
                    mma4(c, al[sub][0], al[sub][1], al[sub][2], al[sub][3], b0, b1);
                    mma4(c + 4, ah[sub][0], ah[sub][1], ah[sub][2], ah[sub][3], b2, b3);
                    mma4(c + 4, al[sub][0], al[sub][1], al[sub][2], al[sub][3], b2, b3);
                }
            }
        }
    }
}

// layer-1: tanh(x @ W1^T + b) into half planes; thread: 1 row x 64 cols
__device__ __forceinline__ void layer1w(Smem& S, const float (*W)[4],
                                        const float* bv, int tid) {
    int row = tid >> 2, cb = (tid & 3) << 6;
    float x0 = S.X[row][0], x1 = S.X[row][1], x2 = S.X[row][2], x3 = S.X[row][3];
    #pragma unroll 4
    for (int j = 0; j < 32; j++) {
        int col = cb + (j << 1);
        const float* w0 = W[col];
        const float* w1 = W[col + 1];
        float z0 = fmaf(x0, w0[0], fmaf(x1, w0[1], fmaf(x2, w0[2], fmaf(x3, w0[3], bv[col]))));
        float z1 = fmaf(x0, w1[0], fmaf(x1, w1[1], fmaf(x2, w1[2], fmaf(x3, w1[3], bv[col + 1]))));
        u32 h, l;
        packp(tanhf(z0), tanhf(z1), h, l);
        *(u32*)&S.AH[row * SA + col] = h;
        *(u32*)&S.AL[row * SA + col] = l;
    }
}

__global__ void __launch_bounds__(NTH, 1)
clf_mma(const float* __restrict__ x,
        const float* __restrict__ Vw1, const float* __restrict__ Vb1,
        const float* __restrict__ Vb2, const float* __restrict__ Vb3,
        const float* __restrict__ Uw1, const float* __restrict__ Ub1,
        const float* __restrict__ Ub2, const float* __restrict__ Uw3,
        const float* __restrict__ Ub3, float* __restrict__ out) {
    extern __shared__ char smraw[];
    Smem& S = *reinterpret_cast<Smem*>(smraw);
    const int tid = threadIdx.x, lane = tid & 31, wid = tid >> 5;
    const int nq = wid & 3, R0n = (wid >> 2) << 5;          // big GEMMs
    const int nh = wid & 1, R0o = (wid >> 1) << 4;          // small GEMMs
    const int r4 = lane >> 2, c2 = (lane & 3) << 1, m = lane >> 3;
    const int rowAo = R0o + r4, rowBo = rowAo + 8;
    const int base = blockIdx.x * CR;

    // ---- parameter staging ----
    for (int i = tid; i < CR * 4; i += NTH) S.X[i >> 2][i & 3] = x[base * 4 + i];
    for (int i = tid; i < 1024; i += NTH) {
        ((float*)S.Vw1s)[i] = Vw1[i];
        ((float*)S.Uw1s)[i] = Uw1[i];
    }
    for (int i = tid; i < 256; i += NTH) {
        S.Vb1s[i] = Vb1[i]; S.Vb2s[i] = Vb2[i];
        S.Ub1s[i] = Ub1[i]; S.Ub2s[i] = Ub2[i]; S.Uw3s[i] = Uw3[i];
    }
    for (int i = tid; i < 64; i += NTH) S.Vb3s[i] = Vb3[i];
    __syncthreads();

    const u32 smAH = s2u(S.AH), smAL = s2u(S.AL), smWH = s2u(S.WH);

    // ---- a1 planes ----
    layer1w(S, S.Vw1s, S.Vb1s, tid);

    // ==== G1: a2 = tanh(a1 @ Vw2^T + b2) ====
    {
        float acc[64];
        #pragma unroll
        for (int i = 0; i < 64; i++) acc[i] = 0.f;
        fwd256h(gVw2s, acc, smAH, smAL, smWH, tid, lane, nq, R0n);
        __syncthreads();  // all a1-plane + WH reads done
        #pragma unroll
        for (int sub = 0; sub < 2; sub++) {
            int rA = R0n + (sub << 4) + r4, rB = rA + 8;
            #pragma unroll
            for (int fp = 0; fp < 4; fp++) {
                float* c = acc + (((sub << 2) + fp) << 3);
                #pragma unroll
                for (int h2 = 0; h2 < 2; h2++) {
                    int n = (nq << 6) + (fp << 4) + (h2 << 3) + c2;
                    u32 h, l;
                    packp(tanhf(c[h2 * 4 + 0] + S.Vb2s[n]),
                          tanhf(c[h2 * 4 + 1] + S.Vb2s[n + 1]), h, l);
                    *(u32*)&S.AH[rA * SA + n] = h;
                    *(u32*)&S.AL[rA * SA + n] = l;
                    packp(tanhf(c[h2 * 4 + 2] + S.Vb2s[n]),
                          tanhf(c[h2 * 4 + 3] + S.Vb2s[n + 1]), h, l);
                    *(u32*)&S.AH[rB * SA + n] = h;
                    *(u32*)&S.AL[rB * SA + n] = l;
                }
            }
        }
    }

    // ==== G2: a3 = tanh(a2 @ Vw3^T + b3); V; w3 frags ====
    u32 w3h[16], w3l[16];
    {
        stageV3A(gVw3s, smWH, tid); CPCOMMIT(); CPWAIT0();
        __syncthreads();   // V3 tile + a2 planes visible
        float a3c[32];
        #pragma unroll
        for (int i = 0; i < 32; i++) a3c[i] = 0.f;
        u32 aoff = ((u32)((lane & 15) * SA + 8 * (lane >> 4))) * 2;
        u32 aHb = smAH + (u32)(R0o * SA) * 2 + aoff;
        u32 aLb = smAL + (u32)(R0o * SA) * 2 + aoff;
        u32 boff3 = ((u32)(((lane & 7) + 8 * (m >> 1)) * SV3 + 8 * (m & 1))) * 2;
        #pragma unroll 1
        for (int q = 0; q < 16; q++) {
            u32 ah0, ah1, ah2, ah3, al0, al1, al2, al3;
            ldsm4(ah0, ah1, ah2, ah3, aHb + (u32)(q << 5));
            ldsm4(al0, al1, al2, al3, aLb + (u32)(q << 5));
            #pragma unroll
            for (int fp = 0; fp < 4; fp++) {
                u32 bb = (u32)((fp << 4) * SV3 + (q << 4)) * 2;
                u32 b0, b1, b2, b3;
                ldsm4(b0, b1, b2, b3, smWH + boff3 + bb);
                float* c = a3c + (fp << 3);
                mma4(c, ah0, ah1, ah2, ah3, b0, b1);
                mma4(c, al0, al1, al2, al3, b0, b1);
                mma4(c + 4, ah0, ah1, ah2, ah3, b2, b3);
                mma4(c + 4, al0, al1, al2, al3, b2, b3);
            }
        }
        float pvA = 0.f, pvB = 0.f;
        #pragma unroll
        for (int f = 0; f < 8; f++) {
            int n = (f << 3) + c2;
            float* c = a3c + ((f >> 1) << 3) + ((f & 1) << 2);
            float v0 = tanhf(c[0] + S.Vb3s[n]);
            float v1 = tanhf(c[1] + S.Vb3s[n + 1]);
            float v2 = tanhf(c[2] + S.Vb3s[n]);
            float v3 = tanhf(c[3] + S.Vb3s[n + 1]);
            pvA += v0 * v0 + v1 * v1;
            pvB += v2 * v2 + v3 * v3;
            int bidx = ((f >> 1) << 2) + ((f & 1) << 1);
            packp(v0 * (1.f - v0 * v0), v1 * (1.f - v1 * v1), w3h[bidx], w3l[bidx]);
            packp(v2 * (1.f - v2 * v2), v3 * (1.f - v3 * v3), w3h[bidx + 1], w3l[bidx + 1]);
        }
        pvA += __shfl_xor_sync(0xffffffffu, pvA, 1);
        pvA += __shfl_xor_sync(0xffffffffu, pvA, 2);
        pvB += __shfl_xor_sync(0xffffffffu, pvB, 1);
        pvB += __shfl_xor_sync(0xffffffffu, pvB, 2);
        if ((lane & 3) == 0 && nh == 0) {
            S.Vpart[rowAo] = pvA;
            S.Vpart[rowBo] = pvB;
        }
    }

    // ==== G3: t2' = (w3 @ Vw3) * (1 - a2^2), planes overwritten ====
    {
        float t2c[64];
        #pragma unroll
        for (int i = 0; i < 64; i++) t2c[i] = 0.f;
        u32 boffB3 = ((u32)(((lane & 7) + 8 * (m & 1)) * SV3 + 8 * (m >> 1))) * 2;
        #pragma unroll
        for (int q = 0; q < 4; q++) {
            int a0 = q << 2;
            #pragma unroll
            for (int fp = 0; fp < 8; fp++) {
                int j0 = (nh << 7) + (fp << 4);
                u32 bb = (u32)((q << 4) * SV3 + j0) * 2;
                u32 b0, b1, b2, b3;
                ldsm4t(b0, b1, b2, b3, smWH + boffB3 + bb);
                float* c = t2c + (fp << 3);
                mma4(c, w3h[a0], w3h[a0 + 1], w3h[a0 + 2], w3h[a0 + 3], b0, b1);
                mma4(c, w3l[a0], w3l[a0 + 1], w3l[a0 + 2], w3l[a0 + 3], b0, b1);
                mma4(c + 4, w3h[a0], w3h[a0 + 1], w3h[a0 + 2], w3h[a0 + 3], b2, b3);
                mma4(c + 4, w3l[a0], w3l[a0 + 1], w3l[a0 + 2], w3l[a0 + 3], b2, b3);
            }
        }
        // mask from a2 planes
        #pragma unroll
        for (int f = 0; f < 16; f++) {
            int n = (nh << 7) + (f << 3) + c2;
            float* c = t2c + ((f >> 1) << 3) + ((f & 1) << 2);
            u32 hA = *(u32*)&S.AH[rowAo * SA + n];
            u32 lA = *(u32*)&S.AL[rowAo * SA + n];
            u32 hB = *(u32*)&S.AH[rowBo * SA + n];
            u32 lB = *(u32*)&S.AL[rowBo * SA + n];
            float ax = hlo(hA) + hlo(lA), ay = hhi(hA) + hhi(lA);
            float bx = hlo(hB) + hlo(lB), by = hhi(hB) + hhi(lB);
            c[0] *= (1.f - ax * ax);
            c[1] *= (1.f - ay * ay);
            c[2] *= (1.f - bx * bx);
            c[3] *= (1.f - by * by);
        }
        __syncthreads();   // all WH + a2-plane reads done
        #pragma unroll
        for (int f = 0; f < 16; f++) {
            int n = (nh << 7) + (f << 3) + c2;
            float* c = t2c + ((f >> 1) << 3) + ((f & 1) << 2);
            u32 h, l;
            packp(c[0], c[1], h, l);
            *(u32*)&S.AH[rowAo * SA + n] = h;
            *(u32*)&S.AL[rowAo * SA + n] = l;
            packp(c[2], c[3], h, l);
            *(u32*)&S.AH[rowBo * SA + n] = h;
            *(u32*)&S.AL[rowBo * SA + n] = l;
        }
    }

    // ==== G4: t1' = (t2' @ Vw2)*(1-a1^2); grad_V = t1' @ Vw1; pipelined ====
    float gpA[4] = {0.f, 0.f, 0.f, 0.f}, gpB[4] = {0.f, 0.f, 0.f, 0.f};
    {
        float xa0 = S.X[rowAo][0], xa1 = S.X[rowAo][1], xa2 = S.X[rowAo][2], xa3 = S.X[rowAo][3];
        float xb0 = S.X[rowBo][0], xb1 = S.X[rowBo][1], xb2 = S.X[rowBo][2], xb3 = S.X[rowBo][3];
        u32 aoff = ((u32)((lane & 15) * SA + 8 * (lane >> 4))) * 2;
        u32 aHb = smAH + (u32)(R0o * SA) * 2 + aoff;
        u32 aLb = smAL + (u32)(R0o * SA) * 2 + aoff;
        u32 boffB = ((u32)(((lane & 7) + 8 * (m & 1)) * SWP + 8 * (m >> 1))) * 2;
        stageA32(gVw2s, smWH, 0, tid); CPCOMMIT();
        #pragma unroll 1
        for (int s = 0; s < 8; s++) {
            CPWAIT0();
            __syncthreads();
            if (s < 7) { stageA32(gVw2s, smWH + ((s + 1) & 1) * BUFB, s + 1, tid); CPCOMMIT(); }
            u32 wb = smWH + (s & 1) * BUFB;
            float c8[8];
            #pragma unroll
            for (int i = 0; i < 8; i++) c8[i] = 0.f;
            #pragma unroll 1
            for (int q = 0; q < 16; q++) {
                u32 ah0, ah1, ah2, ah3, al0, al1, al2, al3;
                ldsm4(ah0, ah1, ah2, ah3, aHb + (u32)(q << 5));
                ldsm4(al0, al1, al2, al3, aLb + (u32)(q << 5));
                u32 bb = (u32)((q << 4) * SWP + (nh << 4)) * 2;
                u32 b0, b1, b2, b3;
                ldsm4t(b0, b1, b2, b3, wb + boffB + bb);
                mma4(c8, ah0, ah1, ah2, ah3, b0, b1);
                mma4(c8, al0, al1, al2, al3, b0, b1);
                mma4(c8 + 4, ah0, ah1, ah2, ah3, b2, b3);
                mma4(c8 + 4, al0, al1, al2, al3, b2, b3);
            }
            #pragma unroll
            for (int f = 0; f < 2; f++) {
                int n = (s << 5) + (nh << 4) + (f << 3) + c2;
                float* c = c8 + (f << 2);
                #pragma unroll
                for (int e = 0; e < 4; e++) {
                    int nn = n + (e & 1);
                    const float* w = S.Vw1s[nn];
                    float z;
                    if (e < 2)
                        z = fmaf(xa0, w[0], fmaf(xa1, w[1], fmaf(xa2, w[2], fmaf(xa3, w[3], S.Vb1s[nn]))));
                    else
                        z = fmaf(xb0, w[0], fmaf(xb1, w[1], fmaf(xb2, w[2], fmaf(xb3, w[3], S.Vb1s[nn]))));
                    float a1v = tanhf(z);
                    float t = c[e] * (1.f - a1v * a1v);
                    float* gp = (e < 2) ? gpA : gpB;
                    gp[0] = fmaf(t, w[0], gp[0]);
                    gp[1] = fmaf(t, w[1], gp[1]);
                    gp[2] = fmaf(t, w[2], gp[2]);
                    gp[3] = fmaf(t, w[3], gp[3]);
                }
            }
        }
        #pragma unroll
        for (int j = 0; j < 4; j++) {
            gpA[j] += __shfl_xor_sync(0xffffffffu, gpA[j], 1);
            gpA[j] += __shfl_xor_sync(0xffffffffu, gpA[j], 2);
            gpB[j] += __shfl_xor_sync(0xffffffffu, gpB[j], 1);
            gpB[j] += __shfl_xor_sync(0xffffffffu, gpB[j], 2);
        }
        if ((lane & 3) == 0) {
            #pragma unroll
            for (int j = 0; j < 4; j++) {
                S.Gpart[rowAo][nh][j] = gpA[j];
                S.Gpart[rowBo][nh][j] = gpB[j];
            }
        }
    }

    // ==== G5: u1 planes + u2 GEMM + fold dot(Uw3) ====
    __syncthreads();
    layer1w(S, S.Uw1s, S.Ub1s, tid);
    {
        float acc[64];
        #pragma unroll
        for (int i = 0; i < 64; i++) acc[i] = 0.f;
        fwd256h(gUw2s, acc, smAH, smAL, smWH, tid, lane, nq, R0n);
        float pu[2][2] = {{0.f, 0.f}, {0.f, 0.f}};
        #pragma unroll
        for (int sub = 0; sub < 2; sub++) {
            #pragma unroll
            for (int fp = 0; fp < 4; fp++) {
                float* c = acc + (((sub << 2) + fp) << 3);
                #pragma unroll
                for (int h2 = 0; h2 < 2; h2++) {
                    int n = (nq << 6) + (fp << 4) + (h2 << 3) + c2;
                    pu[sub][0] = fmaf(tanhf(c[h2 * 4 + 0] + S.Ub2s[n]), S.Uw3s[n], pu[sub][0]);
                    pu[sub][0] = fmaf(tanhf(c[h2 * 4 + 1] + S.Ub2s[n + 1]), S.Uw3s[n + 1], pu[sub][0]);
                    pu[sub][1] = fmaf(tanhf(c[h2 * 4 + 2] + S.Ub2s[n]), S.Uw3s[n], pu[sub][1]);
                    pu[sub][1] = fmaf(tanhf(c[h2 * 4 + 3] + S.Ub2s[n + 1]), S.Uw3s[n + 1], pu[sub][1]);
                }
            }
            pu[sub][0] += __shfl_xor_sync(0xffffffffu, pu[sub][0], 1);
            pu[sub][0] += __shfl_xor_sync(0xffffffffu, pu[sub][0], 2);
            pu[sub][1] += __shfl_xor_sync(0xffffffffu, pu[sub][1], 1);
            pu[sub][1] += __shfl_xor_sync(0xffffffffu, pu[sub][1], 2);
            if ((lane & 3) == 0) {
                S.Upart[R0n + (sub << 4) + r4][nq] = pu[sub][0];
                S.Upart[R0n + (sub << 4) + r4 + 8][nq] = pu[sub][1];
            }
        }
    }
    __syncthreads();

    // ==== final per-row epilogue ====
    if (tid < CR) {
        int b = tid;
        float V = 0.5f * S.Vpart[b];
        float uu = S.Upart[b][0] + S.Upart[b][1] + S.Upart[b][2] + S.Upart[b][3];
        float u = 20.f * tanhf(uu + Ub3[0]);
        float gv0 = S.Gpart[b][0][0] + S.Gpart[b][1][0];
        float gv1 = S.Gpart[b][0][1] + S.Gpart[b][1][1];
        float gv2 = S.Gpart[b][0][2] + S.Gpart[b][1][2];
        float gv3 = S.Gpart[b][0][3] + S.Gpart[b][1][3];
        float th = S.X[b][1], v = S.X[b][2], om = S.X[b][3];
        float s, c;
        sincosf(th, &s, &c);
        float den1 = c - 24.7f, den2 = c * c - 24.7f;
        float f2 = (c * (9.8f * s + 11.5f * v) + 68.4f * v - 1.2f * om * om * s) / den1;
        float f3 = (-58.8f * v * c - 243.5f * v - s * (208.3f + om * om * c)) / den2;
        float g2 = (-1.8f * c - 10.9f) / den1;
        float g3 = (9.3f * c + 38.6f) / den2;
        float Lf = gv0 * v + gv1 * om + gv2 * f2 + gv3 * f3;
        float Lg = gv2 * g2 + gv3 * g3;
        int r = base + b;
        out[r] = u;
        out[BSZ + r] = V;
        out[2 * BSZ + r] = Lf + Lg * u;
    }
}

extern "C" void kernel_launch(void* const* d_in, const int* in_sizes, int n_in,
                              void* d_out, int out_size) {
    const float* x   = (const float*)d_in[0];
    const float* Vw1 = (const float*)d_in[1];
    const float* Vb1 = (const float*)d_in[2];
    const float* Vw2 = (const float*)d_in[3];
    const float* Vb2 = (const float*)d_in[4];
    const float* Vw3 = (const float*)d_in[5];
    const float* Vb3 = (const float*)d_in[6];
    const float* Uw1 = (const float*)d_in[7];
    const float* Ub1 = (const float*)d_in[8];
    const float* Uw2 = (const float*)d_in[9];
    const float* Ub2 = (const float*)d_in[10];
    const float* Uw3 = (const float*)d_in[11];
    const float* Ub3 = (const float*)d_in[12];
    float* out = (float*)d_out;

    prep_kernel<<<288, 512>>>(Vw2, Vw3, Uw2);
    cudaFuncSetAttribute(clf_mma, cudaFuncAttributeMaxDynamicSharedMemorySize,
                         (int)sizeof(Smem));
    clf_mma<<<BSZ / CR, NTH, sizeof(Smem)>>>(
        x, Vw1, Vb1, Vb2, Vb3, Uw1, Ub1, Ub2, Uw3, Ub3, out);
}

// round 15
// speedup vs baseline: 1.5055x; 1.2866x over previous
#include <cuda_runtime.h>
#include <cuda_fp16.h>
#include <math.h>

#define BSZ 131072
#define CR  128
#define NTH 512
#define SA  264   // activation plane stride (half)
#define SWP 40    // pipelined staged tile stride (32 k + 8 pad)
#define SV3 264   // Vw3 full-tile stride
#define BUFB 20480  // bytes per staging buffer (256*40*2)

typedef unsigned int u32;
typedef unsigned short u16;

// ---------------- weight images (half) ----------------
__device__ __align__(16) u16 gVw2s[65536];
__device__ __align__(16) u16 gUw2s[65536];
__device__ __align__(16) u16 gVw3s[16384];

__global__ void prep_kernel(const float* __restrict__ Vw2,
                            const float* __restrict__ Vw3,
                            const float* __restrict__ Uw2) {
    int i = blockIdx.x * blockDim.x + threadIdx.x;
    if (i >= 147456) return;
    float v; u16* dst; int idx;
    if (i < 65536)       { idx = i;          v = Vw2[idx]; dst = gVw2s; }
    else if (i < 131072) { idx = i - 65536;  v = Uw2[idx]; dst = gUw2s; }
    else                 { idx = i - 131072; v = Vw3[idx]; dst = gVw3s; }
    dst[idx] = __half_as_ushort(__float2half_rn(v));
}

// ---------------- smem (~125KB, 1 CTA/SM) ----------------
struct Smem {
    u16 AH[CR * SA];                // activation plane (half)
    u16 WH[20480];                  // double staging buffer / Vw3 full tile
    float X[CR][4];
    float Vw1s[256][4], Uw1s[256][4];
    float Vb1s[256], Vb2s[256], Ub1s[256], Ub2s[256], Uw3s[256];
    float Vb3s[64];
    float Vpart[CR];
    float Upart[CR][4];
    float Gpart[CR][2][4];
};

// ---------------- helpers ----------------
__device__ __forceinline__ u32 s2u(const void* p) {
    u32 a; asm("{ .reg .u64 t; cvta.to.shared.u64 t, %1; cvt.u32.u64 %0, t; }"
               : "=r"(a) : "l"(p));
    return a;
}
#define CPCOMMIT() asm volatile("cp.async.commit_group;" ::: "memory")
#define CPWAIT0()  asm volatile("cp.async.wait_group 0;" ::: "memory")
__device__ __forceinline__ void cp16(u32 dsm, const void* src) {
    asm volatile("cp.async.cg.shared.global [%0], [%1], 16;"
                 :: "r"(dsm), "l"(src) : "memory");
}
__device__ __forceinline__ void ldsm4(u32& r0, u32& r1, u32& r2, u32& r3, u32 a) {
    asm volatile("ldmatrix.sync.aligned.m8n8.x4.shared.b16 {%0,%1,%2,%3}, [%4];"
                 : "=r"(r0), "=r"(r1), "=r"(r2), "=r"(r3) : "r"(a));
}
__device__ __forceinline__ void ldsm4t(u32& r0, u32& r1, u32& r2, u32& r3, u32 a) {
    asm volatile("ldmatrix.sync.aligned.m8n8.x4.trans.shared.b16 {%0,%1,%2,%3}, [%4];"
                 : "=r"(r0), "=r"(r1), "=r"(r2), "=r"(r3) : "r"(a));
}
__device__ __forceinline__ void mma4(float* c, u32 a0, u32 a1, u32 a2, u32 a3,
                                     u32 b0, u32 b1) {
    asm volatile("mma.sync.aligned.m16n8k16.row.col.f32.f16.f16.f32 "
                 "{%0,%1,%2,%3}, {%4,%5,%6,%7}, {%8,%9}, {%0,%1,%2,%3};"
                 : "+f"(c[0]), "+f"(c[1]), "+f"(c[2]), "+f"(c[3])
                 : "r"(a0), "r"(a1), "r"(a2), "r"(a3), "r"(b0), "r"(b1));
}
__device__ __forceinline__ u32 packh(float a, float b) {
    return (u32)__half_as_ushort(__float2half_rn(a)) |
           ((u32)__half_as_ushort(__float2half_rn(b)) << 16);
}
__device__ __forceinline__ float hlo(u32 v) {
    return __half2float(__ushort_as_half((u16)(v & 0xFFFF)));
}
__device__ __forceinline__ float hhi(u32 v) {
    return __half2float(__ushort_as_half((u16)(v >> 16)));
}

// async stage: 256 rows x 32 k-cols (k offset s*32), stride SWP
__device__ __forceinline__ void stageA32(const u16* gw, u32 dsm, int s, int tid) {
    #pragma unroll
    for (int i = tid; i < 1024; i += NTH) {
        int row = i >> 2, u = i & 3;
        cp16(dsm + (u32)(row * SWP + u * 8) * 2,
             gw + row * 256 + (s << 5) + u * 8);
    }
}
// async stage Vw3 full: 64 rows x 256 k-cols, stride SV3
__device__ __forceinline__ void stageV3A(const u16* gw, u32 dsm, int tid) {
    #pragma unroll
    for (int i = tid; i < 2048; i += NTH) {
        int row = i >> 5, u = i & 31;
        cp16(dsm + (u32)(row * SV3 + u * 8) * 2,
             gw + row * 256 + u * 8);
    }
}

// K=256/N=256 forward GEMM, pipelined 8x32k stages, single-term half.
// warp = 32 M-rows (2 sub) x 64 N (quarter nq)
__device__ __forceinline__ void fwd256h(const u16* gw, float* acc,
                                        u32 smAH, u32 smWH,
                                        int tid, int lane, int nq, int R0) {
    u32 aoff = ((u32)((lane & 15) * SA + 8 * (lane >> 4))) * 2;
    int m = lane >> 3;
    u32 boff = ((u32)(((lane & 7) + 8 * (m >> 1)) * SWP + 8 * (m & 1))) * 2;
    u32 aHb = smAH + (u32)(R0 * SA) * 2 + aoff;
    stageA32(gw, smWH, 0, tid); CPCOMMIT();
    #pragma unroll 1
    for (int s = 0; s < 8; s++) {
        CPWAIT0();
        __syncthreads();
        if (s < 7) { stageA32(gw, smWH + ((s + 1) & 1) * BUFB, s + 1, tid); CPCOMMIT(); }
        u32 wb = smWH + (s & 1) * BUFB;
        #pragma unroll
        for (int q = 0; q < 2; q++) {
            int k = (s << 5) + (q << 4);
            u32 ah[2][4];
            #pragma unroll
            for (int sub = 0; sub < 2; sub++) {
                u32 sof = (u32)(sub * 16 * SA + k) * 2;
                ldsm4(ah[sub][0], ah[sub][1], ah[sub][2], ah[sub][3], aHb + sof);
            }
            #pragma unroll
            for (int fp = 0; fp < 4; fp++) {
                int n0 = (nq << 6) + (fp << 4);
                u32 bb = (u32)(n0 * SWP + (q << 4)) * 2;
                u32 b0, b1, b2, b3;
                ldsm4(b0, b1, b2, b3, wb + boff + bb);
                #pragma unroll
                for (int sub = 0; sub < 2; sub++) {
                    float* c = acc + (((sub << 2) + fp) << 3);
                    mma4(c, ah[sub][0], ah[sub][1], ah[sub][2], ah[sub][3], b0, b1);
                    mma4(c + 4, ah[sub][0], ah[sub][1], ah[sub][2], ah[sub][3], b2, b3);
                }
            }
        }
    }
}

// layer-1: tanh(x @ W1^T + b) into half plane; thread: 1 row x 64 cols
__device__ __forceinline__ void layer1w(Smem& S, const float (*W)[4],
                                        const float* bv, int tid) {
    int row = tid >> 2, cb = (tid & 3) << 6;
    float x0 = S.X[row][0], x1 = S.X[row][1], x2 = S.X[row][2], x3 = S.X[row][3];
    #pragma unroll 4
    for (int j = 0; j < 32; j++) {
        int col = cb + (j << 1);
        const float* w0 = W[col];
        const float* w1 = W[col + 1];
        float z0 = fmaf(x0, w0[0], fmaf(x1, w0[1], fmaf(x2, w0[2], fmaf(x3, w0[3], bv[col]))));
        float z1 = fmaf(x0, w1[0], fmaf(x1, w1[1], fmaf(x2, w1[2], fmaf(x3, w1[3], bv[col + 1]))));
        *(u32*)&S.AH[row * SA + col] = packh(tanhf(z0), tanhf(z1));
    }
}

__global__ void __launch_bounds__(NTH, 1)
clf_mma(const float* __restrict__ x,
        const float* __restrict__ Vw1, const float* __restrict__ Vb1,
        const float* __restrict__ Vb2, const float* __restrict__ Vb3,
        const float* __restrict__ Uw1, const float* __restrict__ Ub1,
        const float* __restrict__ Ub2, const float* __restrict__ Uw3,
        const float* __restrict__ Ub3, float* __restrict__ out) {
    extern __shared__ char smraw[];
    Smem& S = *reinterpret_cast<Smem*>(smraw);
    const int tid = threadIdx.x, lane = tid & 31, wid = tid >> 5;
    const int nq = wid & 3, R0n = (wid >> 2) << 5;          // big GEMMs
    const int nh = wid & 1, R0o = (wid >> 1) << 4;          // small GEMMs
    const int r4 = lane >> 2, c2 = (lane & 3) << 1, m = lane >> 3;
    const int rowAo = R0o + r4, rowBo = rowAo + 8;
    const int base = blockIdx.x * CR;

    // ---- parameter staging ----
    for (int i = tid; i < CR * 4; i += NTH) S.X[i >> 2][i & 3] = x[base * 4 + i];
    for (int i = tid; i < 1024; i += NTH) {
        ((float*)S.Vw1s)[i] = Vw1[i];
        ((float*)S.Uw1s)[i] = Uw1[i];
    }
    for (int i = tid; i < 256; i += NTH) {
        S.Vb1s[i] = Vb1[i]; S.Vb2s[i] = Vb2[i];
        S.Ub1s[i] = Ub1[i]; S.Ub2s[i] = Ub2[i]; S.Uw3s[i] = Uw3[i];
    }
    for (int i = tid; i < 64; i += NTH) S.Vb3s[i] = Vb3[i];
    __syncthreads();

    const u32 smAH = s2u(S.AH), smWH = s2u(S.WH);

    // ---- a1 plane ----
    layer1w(S, S.Vw1s, S.Vb1s, tid);

    // ==== G1: a2 = tanh(a1 @ Vw2^T + b2) ====
    {
        float acc[64];
        #pragma unroll
        for (int i = 0; i < 64; i++) acc[i] = 0.f;
        fwd256h(gVw2s, acc, smAH, smWH, tid, lane, nq, R0n);
        __syncthreads();  // all a1-plane + WH reads done
        #pragma unroll
        for (int sub = 0; sub < 2; sub++) {
            int rA = R0n + (sub << 4) + r4, rB = rA + 8;
            #pragma unroll
            for (int fp = 0; fp < 4; fp++) {
                float* c = acc + (((sub << 2) + fp) << 3);
                #pragma unroll
                for (int h2 = 0; h2 < 2; h2++) {
                    int n = (nq << 6) + (fp << 4) + (h2 << 3) + c2;
                    *(u32*)&S.AH[rA * SA + n] =
                        packh(tanhf(c[h2 * 4 + 0] + S.Vb2s[n]),
                              tanhf(c[h2 * 4 + 1] + S.Vb2s[n + 1]));
                    *(u32*)&S.AH[rB * SA + n] =
                        packh(tanhf(c[h2 * 4 + 2] + S.Vb2s[n]),
                              tanhf(c[h2 * 4 + 3] + S.Vb2s[n + 1]));
                }
            }
        }
    }

    // ==== G2: a3 = tanh(a2 @ Vw3^T + b3); V; w3 frags ====
    u32 w3h[16];
    {
        stageV3A(gVw3s, smWH, tid); CPCOMMIT(); CPWAIT0();
        __syncthreads();   // V3 tile + a2 plane visible
        float a3c[32];
        #pragma unroll
        for (int i = 0; i < 32; i++) a3c[i] = 0.f;
        u32 aoff = ((u32)((lane & 15) * SA + 8 * (lane >> 4))) * 2;
        u32 aHb = smAH + (u32)(R0o * SA) * 2 + aoff;
        u32 boff3 = ((u32)(((lane & 7) + 8 * (m >> 1)) * SV3 + 8 * (m & 1))) * 2;
        #pragma unroll 1
        for (int q = 0; q < 16; q++) {
            u32 ah0, ah1, ah2, ah3;
            ldsm4(ah0, ah1, ah2, ah3, aHb + (u32)(q << 5));
            #pragma unroll
            for (int fp = 0; fp < 4; fp++) {
                u32 bb = (u32)((fp << 4) * SV3 + (q << 4)) * 2;
                u32 b0, b1, b2, b3;
                ldsm4(b0, b1, b2, b3, smWH + boff3 + bb);
                float* c = a3c + (fp << 3);
                mma4(c, ah0, ah1, ah2, ah3, b0, b1);
                mma4(c + 4, ah0, ah1, ah2, ah3, b2, b3);
            }
        }
        float pvA = 0.f, pvB = 0.f;
        #pragma unroll
        for (int f = 0; f < 8; f++) {
            int n = (f << 3) + c2;
            float* c = a3c + ((f >> 1) << 3) + ((f & 1) << 2);
            float v0 = tanhf(c[0] + S.Vb3s[n]);
            float v1 = tanhf(c[1] + S.Vb3s[n + 1]);
            float v2 = tanhf(c[2] + S.Vb3s[n]);
            float v3 = tanhf(c[3] + S.Vb3s[n + 1]);
            pvA += v0 * v0 + v1 * v1;
            pvB += v2 * v2 + v3 * v3;
            int bidx = ((f >> 1) << 2) + ((f & 1) << 1);
            w3h[bidx]     = packh(v0 * (1.f - v0 * v0), v1 * (1.f - v1 * v1));
            w3h[bidx + 1] = packh(v2 * (1.f - v2 * v2), v3 * (1.f - v3 * v3));
        }
        pvA += __shfl_xor_sync(0xffffffffu, pvA, 1);
        pvA += __shfl_xor_sync(0xffffffffu, pvA, 2);
        pvB += __shfl_xor_sync(0xffffffffu, pvB, 1);
        pvB += __shfl_xor_sync(0xffffffffu, pvB, 2);
        if ((lane & 3) == 0 && nh == 0) {
            S.Vpart[rowAo] = pvA;
            S.Vpart[rowBo] = pvB;
        }
    }

    // ==== G3: t2' = (w3 @ Vw3) * (1 - a2^2), plane overwritten ====
    {
        float t2c[64];
        #pragma unroll
        for (int i = 0; i < 64; i++) t2c[i] = 0.f;
        u32 boffB3 = ((u32)(((lane & 7) + 8 * (m & 1)) * SV3 + 8 * (m >> 1))) * 2;
        #pragma unroll
        for (int q = 0; q < 4; q++) {
            int a0 = q << 2;
            #pragma unroll
            for (int fp = 0; fp < 8; fp++) {
                int j0 = (nh << 7) + (fp << 4);
                u32 bb = (u32)((q << 4) * SV3 + j0) * 2;
                u32 b0, b1, b2, b3;
                ldsm4t(b0, b1, b2, b3, smWH + boffB3 + bb);
                float* c = t2c + (fp << 3);
                mma4(c, w3h[a0], w3h[a0 + 1], w3h[a0 + 2], w3h[a0 + 3], b0, b1);
                mma4(c + 4, w3h[a0], w3h[a0 + 1], w3h[a0 + 2], w3h[a0 + 3], b2, b3);
            }
        }
        // mask from a2 plane
        #pragma unroll
        for (int f = 0; f < 16; f++) {
            int n = (nh << 7) + (f << 3) + c2;
            float* c = t2c + ((f >> 1) << 3) + ((f & 1) << 2);
            u32 hA = *(u32*)&S.AH[rowAo * SA + n];
            u32 hB = *(u32*)&S.AH[rowBo * SA + n];
            float ax = hlo(hA), ay = hhi(hA);
            float bx = hlo(hB), by = hhi(hB);
            c[0] *= (1.f - ax * ax);
            c[1] *= (1.f - ay * ay);
            c[2] *= (1.f - bx * bx);
            c[3] *= (1.f - by * by);
        }
        __syncthreads();   // all WH + a2-plane reads done
        #pragma unroll
        for (int f = 0; f < 16; f++) {
            int n = (nh << 7) + (f << 3) + c2;
            float* c = t2c + ((f >> 1) << 3) + ((f & 1) << 2);
            *(u32*)&S.AH[rowAo * SA + n] = packh(c[0], c[1]);
            *(u32*)&S.AH[rowBo * SA + n] = packh(c[2], c[3]);
        }
    }

    // ==== G4: t1' = (t2' @ Vw2)*(1-a1^2); grad_V = t1' @ Vw1; pipelined ====
    float gpA[4] = {0.f, 0.f, 0.f, 0.f}, gpB[4] = {0.f, 0.f, 0.f, 0.f};
    {
        float xa0 = S.X[rowAo][0], xa1 = S.X[rowAo][1], xa2 = S.X[rowAo][2], xa3 = S.X[rowAo][3];
        float xb0 = S.X[rowBo][0], xb1 = S.X[rowBo][1], xb2 = S.X[rowBo][2], xb3 = S.X[rowBo][3];
        u32 aoff = ((u32)((lane & 15) * SA + 8 * (lane >> 4))) * 2;
        u32 aHb = smAH + (u32)(R0o * SA) * 2 + aoff;
        u32 boffB = ((u32)(((lane & 7) + 8 * (m & 1)) * SWP + 8 * (m >> 1))) * 2;
        stageA32(gVw2s, smWH, 0, tid); CPCOMMIT();
        #pragma unroll 1
        for (int s = 0; s < 8; s++) {
            CPWAIT0();
            __syncthreads();
            if (s < 7) { stageA32(gVw2s, smWH + ((s + 1) & 1) * BUFB, s + 1, tid); CPCOMMIT(); }
            u32 wb = smWH + (s & 1) * BUFB;
            float c8[8];
            #pragma unroll
            for (int i = 0; i < 8; i++) c8[i] = 0.f;
            #pragma unroll 1
            for (int q = 0; q < 16; q++) {
                u32 ah0, ah1, ah2, ah3;
                ldsm4(ah0, ah1, ah2, ah3, aHb + (u32)(q << 5));
                u32 bb = (u32)((q << 4) * SWP + (nh << 4)) * 2;
                u32 b0, b1, b2, b3;
                ldsm4t(b0, b1, b2, b3, wb + boffB + bb);
                mma4(c8, ah0, ah1, ah2, ah3, b0, b1);
                mma4(c8 + 4, ah0, ah1, ah2, ah3, b2, b3);
            }
            #pragma unroll
            for (int f = 0; f < 2; f++) {
                int n = (s << 5) + (nh << 4) + (f << 3) + c2;
                float* c = c8 + (f << 2);
                #pragma unroll
                for (int e = 0; e < 4; e++) {
                    int nn = n + (e & 1);
                    const float* w = S.Vw1s[nn];
                    float z;
                    if (e < 2)
                        z = fmaf(xa0, w[0], fmaf(xa1, w[1], fmaf(xa2, w[2], fmaf(xa3, w[3], S.Vb1s[nn]))));
                    else
                        z = fmaf(xb0, w[0], fmaf(xb1, w[1], fmaf(xb2, w[2], fmaf(xb3, w[3], S.Vb1s[nn]))));
                    float a1v = tanhf(z);
                    float t = c[e] * (1.f - a1v * a1v);
                    float* gp = (e < 2) ? gpA : gpB;
                    gp[0] = fmaf(t, w[0], gp[0]);
                    gp[1] = fmaf(t, w[1], gp[1]);
                    gp[2] = fmaf(t, w[2], gp[2]);
                    gp[3] = fmaf(t, w[3], gp[3]);
                }
            }
        }
        #pragma unroll
        for (int j = 0; j < 4; j++) {
            gpA[j] += __shfl_xor_sync(0xffffffffu, gpA[j], 1);
            gpA[j] += __shfl_xor_sync(0xffffffffu, gpA[j], 2);
            gpB[j] += __shfl_xor_sync(0xffffffffu, gpB[j], 1);
            gpB[j] += __shfl_xor_sync(0xffffffffu, gpB[j], 2);
        }
        if ((lane & 3) == 0) {
            #pragma unroll
            for (int j = 0; j < 4; j++) {
                S.Gpart[rowAo][nh][j] = gpA[j];
                S.Gpart[rowBo][nh][j] = gpB[j];
            }
        }
    }

    // ==== G5: u1 plane + u2 GEMM + fold dot(Uw3) ====
    __syncthreads();
    layer1w(S, S.Uw1s, S.Ub1s, tid);
    {
        float acc[64];
        #pragma unroll
        for (int i = 0; i < 64; i++) acc[i] = 0.f;
        fwd256h(gUw2s, acc, smAH, smWH, tid, lane, nq, R0n);
        float pu[2][2] = {{0.f, 0.f}, {0.f, 0.f}};
        #pragma unroll
        for (int sub = 0; sub < 2; sub++) {
            #pragma unroll
            for (int fp = 0; fp < 4; fp++) {
                float* c = acc + (((sub << 2) + fp) << 3);
                #pragma unroll
                for (int h2 = 0; h2 < 2; h2++) {
                    int n = (nq << 6) + (fp << 4) + (h2 << 3) + c2;
                    pu[sub][0] = fmaf(tanhf(c[h2 * 4 + 0] + S.Ub2s[n]), S.Uw3s[n], pu[sub][0]);
                    pu[sub][0] = fmaf(tanhf(c[h2 * 4 + 1] + S.Ub2s[n + 1]), S.Uw3s[n + 1], pu[sub][0]);
                    pu[sub][1] = fmaf(tanhf(c[h2 * 4 + 2] + S.Ub2s[n]), S.Uw3s[n], pu[sub][1]);
                    pu[sub][1] = fmaf(tanhf(c[h2 * 4 + 3] + S.Ub2s[n + 1]), S.Uw3s[n + 1], pu[sub][1]);
                }
            }
            pu[sub][0] += __shfl_xor_sync(0xffffffffu, pu[sub][0], 1);
            pu[sub][0] += __shfl_xor_sync(0xffffffffu, pu[sub][0], 2);
            pu[sub][1] += __shfl_xor_sync(0xffffffffu, pu[sub][1], 1);
            pu[sub][1] += __shfl_xor_sync(0xffffffffu, pu[sub][1], 2);
            if ((lane & 3) == 0) {
                S.Upart[R0n + (sub << 4) + r4][nq] = pu[sub][0];
                S.Upart[R0n + (sub << 4) + r4 + 8][nq] = pu[sub][1];
            }
        }
    }
    __syncthreads();

    // ==== final per-row epilogue ====
    if (tid < CR) {
        int b = tid;
        float V = 0.5f * S.Vpart[b];
        float uu = S.Upart[b][0] + S.Upart[b][1] + S.Upart[b][2] + S.Upart[b][3];
        float u = 20.f * tanhf(uu + Ub3[0]);
        float gv0 = S.Gpart[b][0][0] + S.Gpart[b][1][0];
        float gv1 = S.Gpart[b][0][1] + S.Gpart[b][1][1];
        float gv2 = S.Gpart[b][0][2] + S.Gpart[b][1][2];
        float gv3 = S.Gpart[b][0][3] + S.Gpart[b][1][3];
        float th = S.X[b][1], v = S.X[b][2], om = S.X[b][3];
        float s, c;
        sincosf(th, &s, &c);
        float den1 = c - 24.7f, den2 = c * c - 24.7f;
        float f2 = (c * (9.8f * s + 11.5f * v) + 68.4f * v - 1.2f * om * om * s) / den1;
        float f3 = (-58.8f * v * c - 243.5f * v - s * (208.3f + om * om * c)) / den2;
        float g2 = (-1.8f * c - 10.9f) / den1;
        float g3 = (9.3f * c + 38.6f) / den2;
        float Lf = gv0 * v + gv1 * om + gv2 * f2 + gv3 * f3;
        float Lg = gv2 * g2 + gv3 * g3;
        int r = base + b;
        out[r] = u;
        out[BSZ + r] = V;
        out[2 * BSZ + r] = Lf + Lg * u;
    }
}

extern "C" void kernel_launch(void* const* d_in, const int* in_sizes, int n_in,
                              void* d_out, int out_size) {
    const float* x   = (const float*)d_in[0];
    const float* Vw1 = (const float*)d_in[1];
    const float* Vb1 = (const float*)d_in[2];
    const float* Vw2 = (const float*)d_in[3];
    const float* Vb2 = (const float*)d_in[4];
    const float* Vw3 = (const float*)d_in[5];
    const float* Vb3 = (const float*)d_in[6];
    const float* Uw1 = (const float*)d_in[7];
    const float* Ub1 = (const float*)d_in[8];
    const float* Uw2 = (const float*)d_in[9];
    const float* Ub2 = (const float*)d_in[10];
    const float* Uw3 = (const float*)d_in[11];
    const float* Ub3 = (const float*)d_in[12];
    float* out = (float*)d_out;

    prep_kernel<<<288, 512>>>(Vw2, Vw3, Uw2);
    cudaFuncSetAttribute(clf_mma, cudaFuncAttributeMaxDynamicSharedMemorySize,
                         (int)sizeof(Smem));
    clf_mma<<<BSZ / CR, NTH, sizeof(Smem)>>>(
        x, Vw1, Vb1, Vb2, Vb3, Uw1, Ub1, Ub2, Uw3, Ub3, out);
}

// round 16
// speedup vs baseline: 1.5851x; 1.0529x over previous
#include <cuda_runtime.h>
#include <cuda_fp16.h>
#include <math.h>

#define BSZ 131072
#define CR  128
#define NTH 512
#define SA  264   // activation plane stride (half)
#define SWP 40    // pipelined staged tile stride (32 k + 8 pad)
#define SV3 264   // Vw3 full-tile stride
#define S3P 72    // w3 jacobian plane stride
#define BUFB 20480  // bytes per staging buffer (256*40*2)

typedef unsigned int u32;
typedef unsigned short u16;

// ---------------- weight images (half) ----------------
__device__ __align__(16) u16 gVw2s[65536];
__device__ __align__(16) u16 gVw2Ts[65536];   // Vw2^T : [n][k] = Vw2[k][n]
__device__ __align__(16) u16 gUw2s[65536];
__device__ __align__(16) u16 gVw3s[16384];

__global__ void prep_kernel(const float* __restrict__ Vw2,
                            const float* __restrict__ Vw3,
                            const float* __restrict__ Uw2) {
    int i = blockIdx.x * blockDim.x + threadIdx.x;
    if (i >= 212992) return;
    float v; u16* dst; int idx;
    if (i < 65536)       { idx = i;          v = Vw2[idx]; dst = gVw2s; }
    else if (i < 131072) { idx = i - 65536;  int n = idx >> 8, k = idx & 255;
                           v = Vw2[k * 256 + n]; dst = gVw2Ts; }
    else if (i < 196608) { idx = i - 131072; v = Uw2[idx]; dst = gUw2s; }
    else                 { idx = i - 196608; v = Vw3[idx]; dst = gVw3s; }
    dst[idx] = __half_as_ushort(__float2half_rn(v));
}

// ---------------- smem (~154KB, 1 CTA/SM) ----------------
struct Smem {
    u16 AH[CR * SA];                // activation plane (half)
    u16 WH[20480];                  // double staging buffer / Vw3 full tile
    u16 W3P[CR * S3P];              // a3-jacobian plane
    float X[CR][4];
    float Vw1s[256][4], Uw1s[256][4];
    float Vb1s[256], Vb2s[256], Ub1s[256], Ub2s[256], Uw3s[256];
    float Vb3s[64];
    float Vpart[CR];
    float Upart[CR][4];
    float Gpart[CR][4][4];
};

// ---------------- helpers ----------------
__device__ __forceinline__ u32 s2u(const void* p) {
    u32 a; asm("{ .reg .u64 t; cvta.to.shared.u64 t, %1; cvt.u32.u64 %0, t; }"
               : "=r"(a) : "l"(p));
    return a;
}
#define CPCOMMIT() asm volatile("cp.async.commit_group;" ::: "memory")
#define CPWAIT0()  asm volatile("cp.async.wait_group 0;" ::: "memory")
__device__ __forceinline__ void cp16(u32 dsm, const void* src) {
    asm volatile("cp.async.cg.shared.global [%0], [%1], 16;"
                 :: "r"(dsm), "l"(src) : "memory");
}
__device__ __forceinline__ void ldsm4(u32& r0, u32& r1, u32& r2, u32& r3, u32 a) {
    asm volatile("ldmatrix.sync.aligned.m8n8.x4.shared.b16 {%0,%1,%2,%3}, [%4];"
                 : "=r"(r0), "=r"(r1), "=r"(r2), "=r"(r3) : "r"(a));
}
__device__ __forceinline__ void ldsm4t(u32& r0, u32& r1, u32& r2, u32& r3, u32 a) {
    asm volatile("ldmatrix.sync.aligned.m8n8.x4.trans.shared.b16 {%0,%1,%2,%3}, [%4];"
                 : "=r"(r0), "=r"(r1), "=r"(r2), "=r"(r3) : "r"(a));
}
__device__ __forceinline__ void mma4(float* c, u32 a0, u32 a1, u32 a2, u32 a3,
                                     u32 b0, u32 b1) {
    asm volatile("mma.sync.aligned.m16n8k16.row.col.f32.f16.f16.f32 "
                 "{%0,%1,%2,%3}, {%4,%5,%6,%7}, {%8,%9}, {%0,%1,%2,%3};"
                 : "+f"(c[0]), "+f"(c[1]), "+f"(c[2]), "+f"(c[3])
                 : "r"(a0), "r"(a1), "r"(a2), "r"(a3), "r"(b0), "r"(b1));
}
__device__ __forceinline__ u32 packh(float a, float b) {
    return (u32)__half_as_ushort(__float2half_rn(a)) |
           ((u32)__half_as_ushort(__float2half_rn(b)) << 16);
}
__device__ __forceinline__ float hlo(u32 v) {
    return __half2float(__ushort_as_half((u16)(v & 0xFFFF)));
}
__device__ __forceinline__ float hhi(u32 v) {
    return __half2float(__ushort_as_half((u16)(v >> 16)));
}

// async stage: 256 rows x 32 k-cols (k offset s*32), stride SWP
__device__ __forceinline__ void stageA32(const u16* gw, u32 dsm, int s, int tid) {
    #pragma unroll
    for (int i = tid; i < 1024; i += NTH) {
        int row = i >> 2, u = i & 3;
        cp16(dsm + (u32)(row * SWP + u * 8) * 2,
             gw + row * 256 + (s << 5) + u * 8);
    }
}
// async stage Vw3 full: 64 rows x 256 k-cols, stride SV3
__device__ __forceinline__ void stageV3A(const u16* gw, u32 dsm, int tid) {
    #pragma unroll
    for (int i = tid; i < 2048; i += NTH) {
        int row = i >> 5, u = i & 31;
        cp16(dsm + (u32)(row * SV3 + u * 8) * 2,
             gw + row * 256 + u * 8);
    }
}

// K=256/N=256 forward GEMM, pipelined 8x32k stages, single-term half.
// warp = 32 M-rows (2 sub) x 64 N (quarter nq)
__device__ __forceinline__ void fwd256h(const u16* gw, float* acc,
                                        u32 smAH, u32 smWH,
                                        int tid, int lane, int nq, int R0) {
    u32 aoff = ((u32)((lane & 15) * SA + 8 * (lane >> 4))) * 2;
    int m = lane >> 3;
    u32 boff = ((u32)(((lane & 7) + 8 * (m >> 1)) * SWP + 8 * (m & 1))) * 2;
    u32 aHb = smAH + (u32)(R0 * SA) * 2 + aoff;
    stageA32(gw, smWH, 0, tid); CPCOMMIT();
    #pragma unroll 1
    for (int s = 0; s < 8; s++) {
        CPWAIT0();
        __syncthreads();
        if (s < 7) { stageA32(gw, smWH + ((s + 1) & 1) * BUFB, s + 1, tid); CPCOMMIT(); }
        u32 wb = smWH + (s & 1) * BUFB;
        #pragma unroll
        for (int q = 0; q < 2; q++) {
            int k = (s << 5) + (q << 4);
            u32 ah[2][4];
            #pragma unroll
            for (int sub = 0; sub < 2; sub++) {
                u32 sof = (u32)(sub * 16 * SA + k) * 2;
                ldsm4(ah[sub][0], ah[sub][1], ah[sub][2], ah[sub][3], aHb + sof);
            }
            #pragma unroll
            for (int fp = 0; fp < 4; fp++) {
                int n0 = (nq << 6) + (fp << 4);
                u32 bb = (u32)(n0 * SWP + (q << 4)) * 2;
                u32 b0, b1, b2, b3;
                ldsm4(b0, b1, b2, b3, wb + boff + bb);
                #pragma unroll
                for (int sub = 0; sub < 2; sub++) {
                    float* c = acc + (((sub << 2) + fp) << 3);
                    mma4(c, ah[sub][0], ah[sub][1], ah[sub][2], ah[sub][3], b0, b1);
                    mma4(c + 4, ah[sub][0], ah[sub][1], ah[sub][2], ah[sub][3], b2, b3);
                }
            }
        }
    }
}

// layer-1: tanh(x @ W1^T + b) into half plane; thread: 1 row x 64 cols
__device__ __forceinline__ void layer1w(Smem& S, const float (*W)[4],
                                        const float* bv, int tid) {
    int row = tid >> 2, cb = (tid & 3) << 6;
    float x0 = S.X[row][0], x1 = S.X[row][1], x2 = S.X[row][2], x3 = S.X[row][3];
    #pragma unroll 4
    for (int j = 0; j < 32; j++) {
        int col = cb + (j << 1);
        const float* w0 = W[col];
        const float* w1 = W[col + 1];
        float z0 = fmaf(x0, w0[0], fmaf(x1, w0[1], fmaf(x2, w0[2], fmaf(x3, w0[3], bv[col]))));
        float z1 = fmaf(x0, w1[0], fmaf(x1, w1[1], fmaf(x2, w1[2], fmaf(x3, w1[3], bv[col + 1]))));
        *(u32*)&S.AH[row * SA + col] = packh(tanhf(z0), tanhf(z1));
    }
}

__global__ void __launch_bounds__(NTH, 1)
clf_mma(const float* __restrict__ x,
        const float* __restrict__ Vw1, const float* __restrict__ Vb1,
        const float* __restrict__ Vb2, const float* __restrict__ Vb3,
        const float* __restrict__ Uw1, const float* __restrict__ Ub1,
        const float* __restrict__ Ub2, const float* __restrict__ Uw3,
        const float* __restrict__ Ub3, float* __restrict__ out) {
    extern __shared__ char smraw[];
    Smem& S = *reinterpret_cast<Smem*>(smraw);
    const int tid = threadIdx.x, lane = tid & 31, wid = tid >> 5;
    const int nq = wid & 3, R0n = (wid >> 2) << 5;          // big GEMMs
    const int nh = wid & 1, R0o = (wid >> 1) << 4;          // small GEMMs
    const int r4 = lane >> 2, c2 = (lane & 3) << 1, m = lane >> 3;
    const int rowAo = R0o + r4, rowBo = rowAo + 8;
    const int base = blockIdx.x * CR;

    // ---- parameter staging ----
    for (int i = tid; i < CR * 4; i += NTH) S.X[i >> 2][i & 3] = x[base * 4 + i];
    for (int i = tid; i < 1024; i += NTH) {
        ((float*)S.Vw1s)[i] = Vw1[i];
        ((float*)S.Uw1s)[i] = Uw1[i];
    }
    for (int i = tid; i < 256; i += NTH) {
        S.Vb1s[i] = Vb1[i]; S.Vb2s[i] = Vb2[i];
        S.Ub1s[i] = Ub1[i]; S.Ub2s[i] = Ub2[i]; S.Uw3s[i] = Uw3[i];
    }
    for (int i = tid; i < 64; i += NTH) S.Vb3s[i] = Vb3[i];
    __syncthreads();

    const u32 smAH = s2u(S.AH), smWH = s2u(S.WH), smW3P = s2u(S.W3P);

    // ---- a1 plane ----
    layer1w(S, S.Vw1s, S.Vb1s, tid);

    // ==== G1: a2 = tanh(a1 @ Vw2^T + b2) ====
    {
        float acc[64];
        #pragma unroll
        for (int i = 0; i < 64; i++) acc[i] = 0.f;
        fwd256h(gVw2s, acc, smAH, smWH, tid, lane, nq, R0n);
        __syncthreads();  // all a1-plane + WH reads done
        #pragma unroll
        for (int sub = 0; sub < 2; sub++) {
            int rA = R0n + (sub << 4) + r4, rB = rA + 8;
            #pragma unroll
            for (int fp = 0; fp < 4; fp++) {
                float* c = acc + (((sub << 2) + fp) << 3);
                #pragma unroll
                for (int h2 = 0; h2 < 2; h2++) {
                    int n = (nq << 6) + (fp << 4) + (h2 << 3) + c2;
                    *(u32*)&S.AH[rA * SA + n] =
                        packh(tanhf(c[h2 * 4 + 0] + S.Vb2s[n]),
                              tanhf(c[h2 * 4 + 1] + S.Vb2s[n + 1]));
                    *(u32*)&S.AH[rB * SA + n] =
                        packh(tanhf(c[h2 * 4 + 2] + S.Vb2s[n]),
                              tanhf(c[h2 * 4 + 3] + S.Vb2s[n + 1]));
                }
            }
        }
    }

    // ==== G2: a3 = tanh(a2 @ Vw3^T + b3); V; w3 -> W3P plane (nh==0 only) ====
    {
        stageV3A(gVw3s, smWH, tid); CPCOMMIT(); CPWAIT0();
        __syncthreads();   // V3 tile + a2 plane visible
        if (nh == 0) {
            float a3c[32];
            #pragma unroll
            for (int i = 0; i < 32; i++) a3c[i] = 0.f;
            u32 aoff = ((u32)((lane & 15) * SA + 8 * (lane >> 4))) * 2;
            u32 aHb = smAH + (u32)(R0o * SA) * 2 + aoff;
            u32 boff3 = ((u32)(((lane & 7) + 8 * (m >> 1)) * SV3 + 8 * (m & 1))) * 2;
            #pragma unroll 1
            for (int q = 0; q < 16; q++) {
                u32 ah0, ah1, ah2, ah3;
                ldsm4(ah0, ah1, ah2, ah3, aHb + (u32)(q << 5));
                #pragma unroll
                for (int fp = 0; fp < 4; fp++) {
                    u32 bb = (u32)((fp << 4) * SV3 + (q << 4)) * 2;
                    u32 b0, b1, b2, b3;
                    ldsm4(b0, b1, b2, b3, smWH + boff3 + bb);
                    float* c = a3c + (fp << 3);
                    mma4(c, ah0, ah1, ah2, ah3, b0, b1);
                    mma4(c + 4, ah0, ah1, ah2, ah3, b2, b3);
                }
            }
            float pvA = 0.f, pvB = 0.f;
            #pragma unroll
            for (int f = 0; f < 8; f++) {
                int n = (f << 3) + c2;
                float* c = a3c + ((f >> 1) << 3) + ((f & 1) << 2);
                float v0 = tanhf(c[0] + S.Vb3s[n]);
                float v1 = tanhf(c[1] + S.Vb3s[n + 1]);
                float v2 = tanhf(c[2] + S.Vb3s[n]);
                float v3 = tanhf(c[3] + S.Vb3s[n + 1]);
                pvA += v0 * v0 + v1 * v1;
                pvB += v2 * v2 + v3 * v3;
                *(u32*)&S.W3P[rowAo * S3P + n] =
                    packh(v0 * (1.f - v0 * v0), v1 * (1.f - v1 * v1));
                *(u32*)&S.W3P[rowBo * S3P + n] =
                    packh(v2 * (1.f - v2 * v2), v3 * (1.f - v3 * v3));
            }
            pvA += __shfl_xor_sync(0xffffffffu, pvA, 1);
            pvA += __shfl_xor_sync(0xffffffffu, pvA, 2);
            pvB += __shfl_xor_sync(0xffffffffu, pvB, 1);
            pvB += __shfl_xor_sync(0xffffffffu, pvB, 2);
            if ((lane & 3) == 0) {
                S.Vpart[rowAo] = pvA;
                S.Vpart[rowBo] = pvB;
            }
        }
        __syncthreads();   // W3P visible to all warps
    }

    // ==== G3: t2' = (w3 @ Vw3) * (1 - a2^2), plane overwritten ====
    {
        float t2c[64];
        #pragma unroll
        for (int i = 0; i < 64; i++) t2c[i] = 0.f;
        u32 aWb = smW3P + (u32)(R0o * S3P) * 2 +
                  ((u32)((lane & 15) * S3P + 8 * (lane >> 4))) * 2;
        u32 boffB3 = ((u32)(((lane & 7) + 8 * (m & 1)) * SV3 + 8 * (m >> 1))) * 2;
        #pragma unroll
        for (int q = 0; q < 4; q++) {
            u32 w0, w1, w2, w3;
            ldsm4(w0, w1, w2, w3, aWb + (u32)(q << 5));
            #pragma unroll
            for (int fp = 0; fp < 8; fp++) {
                int j0 = (nh << 7) + (fp << 4);
                u32 bb = (u32)((q << 4) * SV3 + j0) * 2;
                u32 b0, b1, b2, b3;
                ldsm4t(b0, b1, b2, b3, smWH + boffB3 + bb);
                float* c = t2c + (fp << 3);
                mma4(c, w0, w1, w2, w3, b0, b1);
                mma4(c + 4, w0, w1, w2, w3, b2, b3);
            }
        }
        // mask from a2 plane
        #pragma unroll
        for (int f = 0; f < 16; f++) {
            int n = (nh << 7) + (f << 3) + c2;
            float* c = t2c + ((f >> 1) << 3) + ((f & 1) << 2);
            u32 hA = *(u32*)&S.AH[rowAo * SA + n];
            u32 hB = *(u32*)&S.AH[rowBo * SA + n];
            float ax = hlo(hA), ay = hhi(hA);
            float bx = hlo(hB), by = hhi(hB);
            c[0] *= (1.f - ax * ax);
            c[1] *= (1.f - ay * ay);
            c[2] *= (1.f - bx * bx);
            c[3] *= (1.f - by * by);
        }
        __syncthreads();   // all WH + a2-plane reads done
        #pragma unroll
        for (int f = 0; f < 16; f++) {
            int n = (nh << 7) + (f << 3) + c2;
            float* c = t2c + ((f >> 1) << 3) + ((f & 1) << 2);
            *(u32*)&S.AH[rowAo * SA + n] = packh(c[0], c[1]);
            *(u32*)&S.AH[rowBo * SA + n] = packh(c[2], c[3]);
        }
    }

    // ==== G4: t1'raw = t2' @ Vw2T (fwd mapping, pipelined);
    //          epi folds (1-a1^2) mask + grad_V = t1' @ Vw1 ====
    {
        float acc[64];
        #pragma unroll
        for (int i = 0; i < 64; i++) acc[i] = 0.f;
        fwd256h(gVw2Ts, acc, smAH, smWH, tid, lane, nq, R0n);
        float gp[4][4];
        #pragma unroll
        for (int sr = 0; sr < 4; sr++)
            #pragma unroll
            for (int j = 0; j < 4; j++) gp[sr][j] = 0.f;
        #pragma unroll
        for (int sub = 0; sub < 2; sub++) {
            int rA = R0n + (sub << 4) + r4, rB = rA + 8;
            float xa0 = S.X[rA][0], xa1 = S.X[rA][1], xa2 = S.X[rA][2], xa3 = S.X[rA][3];
            float xb0 = S.X[rB][0], xb1 = S.X[rB][1], xb2 = S.X[rB][2], xb3 = S.X[rB][3];
            #pragma unroll
            for (int fp = 0; fp < 4; fp++) {
                float* c = acc + (((sub << 2) + fp) << 3);
                #pragma unroll
                for (int h2 = 0; h2 < 2; h2++) {
                    int n = (nq << 6) + (fp << 4) + (h2 << 3) + c2;
                    #pragma unroll
                    for (int e = 0; e < 4; e++) {
                        int nn = n + (e & 1);
                        const float* w = S.Vw1s[nn];
                        float z;
                        if (e < 2)
                            z = fmaf(xa0, w[0], fmaf(xa1, w[1], fmaf(xa2, w[2], fmaf(xa3, w[3], S.Vb1s[nn]))));
                        else
                            z = fmaf(xb0, w[0], fmaf(xb1, w[1], fmaf(xb2, w[2], fmaf(xb3, w[3], S.Vb1s[nn]))));
                        float a1v = tanhf(z);
                        float t = c[h2 * 4 + e] * (1.f - a1v * a1v);
                        float* g = gp[(sub << 1) + (e >> 1)];
                        g[0] = fmaf(t, w[0], g[0]);
                        g[1] = fmaf(t, w[1], g[1]);
                        g[2] = fmaf(t, w[2], g[2]);
                        g[3] = fmaf(t, w[3], g[3]);
                    }
                }
            }
        }
        #pragma unroll
        for (int sr = 0; sr < 4; sr++) {
            int row = R0n + ((sr >> 1) << 4) + ((sr & 1) << 3) + r4;
            #pragma unroll
            for (int j = 0; j < 4; j++) {
                float v = gp[sr][j];
                v += __shfl_xor_sync(0xffffffffu, v, 1);
                v += __shfl_xor_sync(0xffffffffu, v, 2);
                if ((lane & 3) == 0) S.Gpart[row][nq][j] = v;
            }
        }
    }

    // ==== G5: u1 plane + u2 GEMM + fold dot(Uw3) ====
    __syncthreads();
    layer1w(S, S.Uw1s, S.Ub1s, tid);
    {
        float acc[64];
        #pragma unroll
        for (int i = 0; i < 64; i++) acc[i] = 0.f;
        fwd256h(gUw2s, acc, smAH, smWH, tid, lane, nq, R0n);
        float pu[2][2] = {{0.f, 0.f}, {0.f, 0.f}};
        #pragma unroll
        for (int sub = 0; sub < 2; sub++) {
            #pragma unroll
            for (int fp = 0; fp < 4; fp++) {
                float* c = acc + (((sub << 2) + fp) << 3);
                #pragma unroll
                for (int h2 = 0; h2 < 2; h2++) {
                    int n = (nq << 6) + (fp << 4) + (h2 << 3) + c2;
                    pu[sub][0] = fmaf(tanhf(c[h2 * 4 + 0] + S.Ub2s[n]), S.Uw3s[n], pu[sub][0]);
                    pu[sub][0] = fmaf(tanhf(c[h2 * 4 + 1] + S.Ub2s[n + 1]), S.Uw3s[n + 1], pu[sub][0]);
                    pu[sub][1] = fmaf(tanhf(c[h2 * 4 + 2] + S.Ub2s[n]), S.Uw3s[n], pu[sub][1]);
                    pu[sub][1] = fmaf(tanhf(c[h2 * 4 + 3] + S.Ub2s[n + 1]), S.Uw3s[n + 1], pu[sub][1]);
                }
            }
            pu[sub][0] += __shfl_xor_sync(0xffffffffu, pu[sub][0], 1);
            pu[sub][0] += __shfl_xor_sync(0xffffffffu, pu[sub][0], 2);
            pu[sub][1] += __shfl_xor_sync(0xffffffffu, pu[sub][1], 1);
            pu[sub][1] += __shfl_xor_sync(0xffffffffu, pu[sub][1], 2);
            if ((lane & 3) == 0) {
                S.Upart[R0n + (sub << 4) + r4][nq] = pu[sub][0];
                S.Upart[R0n + (sub << 4) + r4 + 8][nq] = pu[sub][1];
            }
        }
    }
    __syncthreads();

    // ==== final per-row epilogue ====
    if (tid < CR) {
        int b = tid;
        float V = 0.5f * S.Vpart[b];
        float uu = S.Upart[b][0] + S.Upart[b][1] + S.Upart[b][2] + S.Upart[b][3];
        float u = 20.f * tanhf(uu + Ub3[0]);
        float gv0 = S.Gpart[b][0][0] + S.Gpart[b][1][0] + S.Gpart[b][2][0] + S.Gpart[b][3][0];
        float gv1 = S.Gpart[b][0][1] + S.Gpart[b][1][1] + S.Gpart[b][2][1] + S.Gpart[b][3][1];
        float gv2 = S.Gpart[b][0][2] + S.Gpart[b][1][2] + S.Gpart[b][2][2] + S.Gpart[b][3][2];
        float gv3 = S.Gpart[b][0][3] + S.Gpart[b][1][3] + S.Gpart[b][2][3] + S.Gpart[b][3][3];
        float th = S.X[b][1], v = S.X[b][2], om = S.X[b][3];
        float s, c;
        sincosf(th, &s, &c);
        float den1 = c - 24.7f, den2 = c * c - 24.7f;
        float f2 = (c * (9.8f * s + 11.5f * v) + 68.4f * v - 1.2f * om * om * s) / den1;
        float f3 = (-58.8f * v * c - 243.5f * v - s * (208.3f + om * om * c)) / den2;
        float g2 = (-1.8f * c - 10.9f) / den1;
        float g3 = (9.3f * c + 38.6f) / den2;
        float Lf = gv0 * v + gv1 * om + gv2 * f2 + gv3 * f3;
        float Lg = gv2 * g2 + gv3 * g3;
        int r = base + b;
        out[r] = u;
        out[BSZ + r] = V;
        out[2 * BSZ + r] = Lf + Lg * u;
    }
}

extern "C" void kernel_launch(void* const* d_in, const int* in_sizes, int n_in,
                              void* d_out, int out_size) {
    const float* x   = (const float*)d_in[0];
    const float* Vw1 = (const float*)d_in[1];
    const float* Vb1 = (const float*)d_in[2];
    const float* Vw2 = (const float*)d_in[3];
    const float* Vb2 = (const float*)d_in[4];
    const float* Vw3 = (const float*)d_in[5];
    const float* Vb3 = (const float*)d_in[6];
    const float* Uw1 = (const float*)d_in[7];
    const float* Ub1 = (const float*)d_in[8];
    const float* Uw2 = (const float*)d_in[9];
    const float* Ub2 = (const float*)d_in[10];
    const float* Uw3 = (const float*)d_in[11];
    const float* Ub3 = (const float*)d_in[12];
    float* out = (float*)d_out;

    prep_kernel<<<416, 512>>>(Vw2, Vw3, Uw2);
    cudaFuncSetAttribute(clf_mma, cudaFuncAttributeMaxDynamicSharedMemorySize,
                         (int)sizeof(Smem));
    clf_mma<<<BSZ / CR, NTH, sizeof(Smem)>>>(
        x, Vw1, Vb1, Vb2, Vb3, Uw1, Ub1, Ub2, Uw3, Ub3, out);
}

// round 17
// speedup vs baseline: 1.6980x; 1.0712x over previous
#include <cuda_runtime.h>
#include <cuda_fp16.h>
#include <math.h>

#define BSZ 131072
#define CR  128
#define NTH 512
#define SA  264    // activation plane stride (half)
#define SWP 72     // pipelined staged tile stride (64 k + 8 pad)
#define SV3 264    // Vw3 full-tile stride
#define S3P 72     // w3 jacobian plane stride
#define BUFB 36864 // bytes per staging buffer (256*72*2)

typedef unsigned int u32;
typedef unsigned short u16;

// ---------------- weight images (half) ----------------
__device__ __align__(16) u16 gVw2s[65536];
__device__ __align__(16) u16 gVw2Ts[65536];   // Vw2^T : [n][k] = Vw2[k][n]
__device__ __align__(16) u16 gUw2s[65536];
__device__ __align__(16) u16 gVw3s[16384];

__global__ void prep_kernel(const float* __restrict__ Vw2,
                            const float* __restrict__ Vw3,
                            const float* __restrict__ Uw2) {
    int i = blockIdx.x * blockDim.x + threadIdx.x;
    if (i >= 212992) return;
    float v; u16* dst; int idx;
    if (i < 65536)       { idx = i;          v = Vw2[idx]; dst = gVw2s; }
    else if (i < 131072) { idx = i - 65536;  int n = idx >> 8, k = idx & 255;
                           v = Vw2[k * 256 + n]; dst = gVw2Ts; }
    else if (i < 196608) { idx = i - 131072; v = Uw2[idx]; dst = gUw2s; }
    else                 { idx = i - 196608; v = Vw3[idx]; dst = gVw3s; }
    dst[idx] = __half_as_ushort(__float2half_rn(v));
}

// ---------------- smem (~186KB, 1 CTA/SM) ----------------
struct Smem {
    u16 AH[CR * SA];                // activation plane (half)
    u16 WH[36864];                  // double staging buffer (2 x BUFB)
    u16 W3P[CR * S3P];              // a3-jacobian plane
    float X[CR][4];
    float Vw1s[256][4], Uw1s[256][4];
    float Vb1s[256], Vb2s[256], Ub1s[256], Ub2s[256], Uw3s[256];
    float Vb3s[64];
    float Vpart[CR];
    float Upart[CR][4];
    float Gpart[CR][4][4];
};

// ---------------- helpers ----------------
__device__ __forceinline__ u32 s2u(const void* p) {
    u32 a; asm("{ .reg .u64 t; cvta.to.shared.u64 t, %1; cvt.u32.u64 %0, t; }"
               : "=r"(a) : "l"(p));
    return a;
}
#define CPCOMMIT() asm volatile("cp.async.commit_group;" ::: "memory")
#define CPWAIT0()  asm volatile("cp.async.wait_group 0;" ::: "memory")
__device__ __forceinline__ void cp16(u32 dsm, const void* src) {
    asm volatile("cp.async.cg.shared.global [%0], [%1], 16;"
                 :: "r"(dsm), "l"(src) : "memory");
}
__device__ __forceinline__ void ldsm4(u32& r0, u32& r1, u32& r2, u32& r3, u32 a) {
    asm volatile("ldmatrix.sync.aligned.m8n8.x4.shared.b16 {%0,%1,%2,%3}, [%4];"
                 : "=r"(r0), "=r"(r1), "=r"(r2), "=r"(r3) : "r"(a));
}
__device__ __forceinline__ void ldsm4t(u32& r0, u32& r1, u32& r2, u32& r3, u32 a) {
    asm volatile("ldmatrix.sync.aligned.m8n8.x4.trans.shared.b16 {%0,%1,%2,%3}, [%4];"
                 : "=r"(r0), "=r"(r1), "=r"(r2), "=r"(r3) : "r"(a));
}
__device__ __forceinline__ void mma4(float* c, u32 a0, u32 a1, u32 a2, u32 a3,
                                     u32 b0, u32 b1) {
    asm volatile("mma.sync.aligned.m16n8k16.row.col.f32.f16.f16.f32 "
                 "{%0,%1,%2,%3}, {%4,%5,%6,%7}, {%8,%9}, {%0,%1,%2,%3};"
                 : "+f"(c[0]), "+f"(c[1]), "+f"(c[2]), "+f"(c[3])
                 : "r"(a0), "r"(a1), "r"(a2), "r"(a3), "r"(b0), "r"(b1));
}
__device__ __forceinline__ u32 packh(float a, float b) {
    return (u32)__half_as_ushort(__float2half_rn(a)) |
           ((u32)__half_as_ushort(__float2half_rn(b)) << 16);
}
__device__ __forceinline__ float hlo(u32 v) {
    return __half2float(__ushort_as_half((u16)(v & 0xFFFF)));
}
__device__ __forceinline__ float hhi(u32 v) {
    return __half2float(__ushort_as_half((u16)(v >> 16)));
}

// async stage: 256 rows x 64 k-cols (k offset s*64), stride SWP
__device__ __forceinline__ void stageA64(const u16* gw, u32 dsm, int s, int tid) {
    #pragma unroll
    for (int i = tid; i < 2048; i += NTH) {
        int row = i >> 3, u = i & 7;
        cp16(dsm + (u32)(row * SWP + u * 8) * 2,
             gw + row * 256 + (s << 6) + u * 8);
    }
}
// async stage Vw3 full: 64 rows x 256 k-cols, stride SV3 (fits buffer0)
__device__ __forceinline__ void stageV3A(const u16* gw, u32 dsm, int tid) {
    #pragma unroll
    for (int i = tid; i < 2048; i += NTH) {
        int row = i >> 5, u = i & 31;
        cp16(dsm + (u32)(row * SV3 + u * 8) * 2,
             gw + row * 256 + u * 8);
    }
}

// K=256/N=256 forward GEMM, 4 pipelined 64-k stages, buffer parity P.
// Caller MUST pre-issue slice 0 into buffer (P&1) and CPCOMMIT before calling.
// warp = 32 M-rows (2 sub) x 64 N (quarter nq)
template <int P>
__device__ __forceinline__ void fwd256h(const u16* gw, float* acc,
                                        u32 smAH, u32 smWH,
                                        int tid, int lane, int nq, int R0) {
    u32 aoff = ((u32)((lane & 15) * SA + 8 * (lane >> 4))) * 2;
    int m = lane >> 3;
    u32 boff = ((u32)(((lane & 7) + 8 * (m >> 1)) * SWP + 8 * (m & 1))) * 2;
    u32 aHb = smAH + (u32)(R0 * SA) * 2 + aoff;
    #pragma unroll 1
    for (int s = 0; s < 4; s++) {
        CPWAIT0();
        __syncthreads();
        if (s < 3) {
            stageA64(gw, smWH + (u32)((s + 1 + P) & 1) * BUFB, s + 1, tid);
            CPCOMMIT();
        }
        u32 wb = smWH + (u32)((s + P) & 1) * BUFB;
        #pragma unroll
        for (int q = 0; q < 4; q++) {
            int k = (s << 6) + (q << 4);
            u32 ah[2][4];
            #pragma unroll
            for (int sub = 0; sub < 2; sub++) {
                u32 sof = (u32)(sub * 16 * SA + k) * 2;
                ldsm4(ah[sub][0], ah[sub][1], ah[sub][2], ah[sub][3], aHb + sof);
            }
            #pragma unroll
            for (int fp = 0; fp < 4; fp++) {
                int n0 = (nq << 6) + (fp << 4);
                u32 bb = (u32)(n0 * SWP + (q << 4)) * 2;
                u32 b0, b1, b2, b3;
                ldsm4(b0, b1, b2, b3, wb + boff + bb);
                #pragma unroll
                for (int sub = 0; sub < 2; sub++) {
                    float* c = acc + (((sub << 2) + fp) << 3);
                    mma4(c, ah[sub][0], ah[sub][1], ah[sub][2], ah[sub][3], b0, b1);
                    mma4(c + 4, ah[sub][0], ah[sub][1], ah[sub][2], ah[sub][3], b2, b3);
                }
            }
        }
    }
}

// layer-1: tanh(x @ W1^T + b) into half plane; thread: 1 row x 64 cols
__device__ __forceinline__ void layer1w(Smem& S, const float (*W)[4],
                                        const float* bv, int tid) {
    int row = tid >> 2, cb = (tid & 3) << 6;
    float x0 = S.X[row][0], x1 = S.X[row][1], x2 = S.X[row][2], x3 = S.X[row][3];
    #pragma unroll 4
    for (int j = 0; j < 32; j++) {
        int col = cb + (j << 1);
        const float* w0 = W[col];
        const float* w1 = W[col + 1];
        float z0 = fmaf(x0, w0[0], fmaf(x1, w0[1], fmaf(x2, w0[2], fmaf(x3, w0[3], bv[col]))));
        float z1 = fmaf(x0, w1[0], fmaf(x1, w1[1], fmaf(x2, w1[2], fmaf(x3, w1[3], bv[col + 1]))));
        *(u32*)&S.AH[row * SA + col] = packh(tanhf(z0), tanhf(z1));
    }
}

__global__ void __launch_bounds__(NTH, 1)
clf_mma(const float* __restrict__ x,
        const float* __restrict__ Vw1, const float* __restrict__ Vb1,
        const float* __restrict__ Vb2, const float* __restrict__ Vb3,
        const float* __restrict__ Uw1, const float* __restrict__ Ub1,
        const float* __restrict__ Ub2, const float* __restrict__ Uw3,
        const float* __restrict__ Ub3, float* __restrict__ out) {
    extern __shared__ char smraw[];
    Smem& S = *reinterpret_cast<Smem*>(smraw);
    const int tid = threadIdx.x, lane = tid & 31, wid = tid >> 5;
    const int nq = wid & 3, R0n = (wid >> 2) << 5;          // big GEMMs
    const int nh = wid & 1, R0o = (wid >> 1) << 4;          // small GEMMs
    const int r4 = lane >> 2, c2 = (lane & 3) << 1, m = lane >> 3;
    const int rowAo = R0o + r4, rowBo = rowAo + 8;
    const int base = blockIdx.x * CR;

    // ---- parameter staging ----
    for (int i = tid; i < CR * 4; i += NTH) S.X[i >> 2][i & 3] = x[base * 4 + i];
    for (int i = tid; i < 1024; i += NTH) {
        ((float*)S.Vw1s)[i] = Vw1[i];
        ((float*)S.Uw1s)[i] = Uw1[i];
    }
    for (int i = tid; i < 256; i += NTH) {
        S.Vb1s[i] = Vb1[i]; S.Vb2s[i] = Vb2[i];
        S.Ub1s[i] = Ub1[i]; S.Ub2s[i] = Ub2[i]; S.Uw3s[i] = Uw3[i];
    }
    for (int i = tid; i < 64; i += NTH) S.Vb3s[i] = Vb3[i];

    const u32 smAH = s2u(S.AH), smWH = s2u(S.WH), smW3P = s2u(S.W3P);

    // prefetch G1 slice0 (buffer0) while layer-1 computes
    stageA64(gVw2s, smWH, 0, tid); CPCOMMIT();
    __syncthreads();   // params visible

    // ---- a1 plane ----
    layer1w(S, S.Vw1s, S.Vb1s, tid);

    // ==== G1: a2 = tanh(a1 @ Vw2^T + b2) ====
    {
        float acc[64];
        #pragma unroll
        for (int i = 0; i < 64; i++) acc[i] = 0.f;
        fwd256h<0>(gVw2s, acc, smAH, smWH, tid, lane, nq, R0n);
        // prefetch Vw3 tile into buffer0 (free after G1's s=3 top sync)
        stageV3A(gVw3s, smWH, tid); CPCOMMIT();
        __syncthreads();  // all a1-plane reads done before overwrite
        #pragma unroll
        for (int sub = 0; sub < 2; sub++) {
            int rA = R0n + (sub << 4) + r4, rB = rA + 8;
            #pragma unroll
            for (int fp = 0; fp < 4; fp++) {
                float* c = acc + (((sub << 2) + fp) << 3);
                #pragma unroll
                for (int h2 = 0; h2 < 2; h2++) {
                    int n = (nq << 6) + (fp << 4) + (h2 << 3) + c2;
                    *(u32*)&S.AH[rA * SA + n] =
                        packh(tanhf(c[h2 * 4 + 0] + S.Vb2s[n]),
                              tanhf(c[h2 * 4 + 1] + S.Vb2s[n + 1]));
                    *(u32*)&S.AH[rB * SA + n] =
                        packh(tanhf(c[h2 * 4 + 2] + S.Vb2s[n]),
                              tanhf(c[h2 * 4 + 3] + S.Vb2s[n + 1]));
                }
            }
        }
    }

    // ==== G2: a3 = tanh(a2 @ Vw3^T + b3); V; w3 -> W3P plane (nh==0 only) ====
    {
        CPWAIT0();
        __syncthreads();   // V3 tile + a2 plane visible
        // prefetch G4 slice0 into buffer1 (covered by G2+G3 compute)
        stageA64(gVw2Ts, smWH + BUFB, 0, tid); CPCOMMIT();
        if (nh == 0) {
            float a3c[32];
            #pragma unroll
            for (int i = 0; i < 32; i++) a3c[i] = 0.f;
            u32 aoff = ((u32)((lane & 15) * SA + 8 * (lane >> 4))) * 2;
            u32 aHb = smAH + (u32)(R0o * SA) * 2 + aoff;
            u32 boff3 = ((u32)(((lane & 7) + 8 * (m >> 1)) * SV3 + 8 * (m & 1))) * 2;
            #pragma unroll 1
            for (int q = 0; q < 16; q++) {
                u32 ah0, ah1, ah2, ah3;
                ldsm4(ah0, ah1, ah2, ah3, aHb + (u32)(q << 5));
                #pragma unroll
                for (int fp = 0; fp < 4; fp++) {
                    u32 bb = (u32)((fp << 4) * SV3 + (q << 4)) * 2;
                    u32 b0, b1, b2, b3;
                    ldsm4(b0, b1, b2, b3, smWH + boff3 + bb);
                    float* c = a3c + (fp << 3);
                    mma4(c, ah0, ah1, ah2, ah3, b0, b1);
                    mma4(c + 4, ah0, ah1, ah2, ah3, b2, b3);
                }
            }
            float pvA = 0.f, pvB = 0.f;
            #pragma unroll
            for (int f = 0; f < 8; f++) {
                int n = (f << 3) + c2;
                float* c = a3c + ((f >> 1) << 3) + ((f & 1) << 2);
                float v0 = tanhf(c[0] + S.Vb3s[n]);
                float v1 = tanhf(c[1] + S.Vb3s[n + 1]);
                float v2 = tanhf(c[2] + S.Vb3s[n]);
                float v3 = tanhf(c[3] + S.Vb3s[n + 1]);
                pvA += v0 * v0 + v1 * v1;
                pvB += v2 * v2 + v3 * v3;
                *(u32*)&S.W3P[rowAo * S3P + n] =
                    packh(v0 * (1.f - v0 * v0), v1 * (1.f - v1 * v1));
                *(u32*)&S.W3P[rowBo * S3P + n] =
                    packh(v2 * (1.f - v2 * v2), v3 * (1.f - v3 * v3));
            }
            pvA += __shfl_xor_sync(0xffffffffu, pvA, 1);
            pvA += __shfl_xor_sync(0xffffffffu, pvA, 2);
            pvB += __shfl_xor_sync(0xffffffffu, pvB, 1);
            pvB += __shfl_xor_sync(0xffffffffu, pvB, 2);
            if ((lane & 3) == 0) {
                S.Vpart[rowAo] = pvA;
                S.Vpart[rowBo] = pvB;
            }
        }
        __syncthreads();   // W3P visible to all warps
    }

    // ==== G3: t2' = (w3 @ Vw3) * (1 - a2^2), plane overwritten ====
    {
        float t2c[64];
        #pragma unroll
        for (int i = 0; i < 64; i++) t2c[i] = 0.f;
        u32 aWb = smW3P + (u32)(R0o * S3P) * 2 +
                  ((u32)((lane & 15) * S3P + 8 * (lane >> 4))) * 2;
        u32 boffB3 = ((u32)(((lane & 7) + 8 * (m & 1)) * SV3 + 8 * (m >> 1))) * 2;
        #pragma unroll
        for (int q = 0; q < 4; q++) {
            u32 w0, w1, w2, w3;
            ldsm4(w0, w1, w2, w3, aWb + (u32)(q << 5));
            #pragma unroll
            for (int fp = 0; fp < 8; fp++) {
                int j0 = (nh << 7) + (fp << 4);
                u32 bb = (u32)((q << 4) * SV3 + j0) * 2;
                u32 b0, b1, b2, b3;
                ldsm4t(b0, b1, b2, b3, smWH + boffB3 + bb);
                float* c = t2c + (fp << 3);
                mma4(c, w0, w1, w2, w3, b0, b1);
                mma4(c + 4, w0, w1, w2, w3, b2, b3);
            }
        }
        // mask from a2 plane
        #pragma unroll
        for (int f = 0; f < 16; f++) {
            int n = (nh << 7) + (f << 3) + c2;
            float* c = t2c + ((f >> 1) << 3) + ((f & 1) << 2);
            u32 hA = *(u32*)&S.AH[rowAo * SA + n];
            u32 hB = *(u32*)&S.AH[rowBo * SA + n];
            float ax = hlo(hA), ay = hhi(hA);
            float bx = hlo(hB), by = hhi(hB);
            c[0] *= (1.f - ax * ax);
            c[1] *= (1.f - ay * ay);
            c[2] *= (1.f - bx * bx);
            c[3] *= (1.f - by * by);
        }
        __syncthreads();   // V3-tile + a2-plane reads done
        #pragma unroll
        for (int f = 0; f < 16; f++) {
            int n = (nh << 7) + (f << 3) + c2;
            float* c = t2c + ((f >> 1) << 3) + ((f & 1) << 2);
            *(u32*)&S.AH[rowAo * SA + n] = packh(c[0], c[1]);
            *(u32*)&S.AH[rowBo * SA + n] = packh(c[2], c[3]);
        }
    }

    // ==== G4: t1'raw = t2' @ Vw2T (fwd mapping, parity 1);
    //          epi folds (1-a1^2) mask + grad_V = t1' @ Vw1 ====
    {
        float acc[64];
        #pragma unroll
        for (int i = 0; i < 64; i++) acc[i] = 0.f;
        fwd256h<1>(gVw2Ts, acc, smAH, smWH, tid, lane, nq, R0n);
        // prefetch G5 slice0 into buffer1 (free after G4's s=3 top sync)
        stageA64(gUw2s, smWH + BUFB, 0, tid); CPCOMMIT();
        float gp[4][4];
        #pragma unroll
        for (int sr = 0; sr < 4; sr++)
            #pragma unroll
            for (int j = 0; j < 4; j++) gp[sr][j] = 0.f;
        #pragma unroll
        for (int sub = 0; sub < 2; sub++) {
            int rA = R0n + (sub << 4) + r4, rB = rA + 8;
            float xa0 = S.X[rA][0], xa1 = S.X[rA][1], xa2 = S.X[rA][2], xa3 = S.X[rA][3];
            float xb0 = S.X[rB][0], xb1 = S.X[rB][1], xb2 = S.X[rB][2], xb3 = S.X[rB][3];
            #pragma unroll
            for (int fp = 0; fp < 4; fp++) {
                float* c = acc + (((sub << 2) + fp) << 3);
                #pragma unroll
                for (int h2 = 0; h2 < 2; h2++) {
                    int n = (nq << 6) + (fp << 4) + (h2 << 3) + c2;
                    #pragma unroll
                    for (int e = 0; e < 4; e++) {
                        int nn = n + (e & 1);
                        const float* w = S.Vw1s[nn];
                        float z;
                        if (e < 2)
                            z = fmaf(xa0, w[0], fmaf(xa1, w[1], fmaf(xa2, w[2], fmaf(xa3, w[3], S.Vb1s[nn]))));
                        else
                            z = fmaf(xb0, w[0], fmaf(xb1, w[1], fmaf(xb2, w[2], fmaf(xb3, w[3], S.Vb1s[nn]))));
                        float a1v = tanhf(z);
                        float t = c[h2 * 4 + e] * (1.f - a1v * a1v);
                        float* g = gp[(sub << 1) + (e >> 1)];
                        g[0] = fmaf(t, w[0], g[0]);
                        g[1] = fmaf(t, w[1], g[1]);
                        g[2] = fmaf(t, w[2], g[2]);
                        g[3] = fmaf(t, w[3], g[3]);
                    }
                }
            }
        }
        #pragma unroll
        for (int sr = 0; sr < 4; sr++) {
            int row = R0n + ((sr >> 1) << 4) + ((sr & 1) << 3) + r4;
            #pragma unroll
            for (int j = 0; j < 4; j++) {
                float v = gp[sr][j];
                v += __shfl_xor_sync(0xffffffffu, v, 1);
                v += __shfl_xor_sync(0xffffffffu, v, 2);
                if ((lane & 3) == 0) S.Gpart[row][nq][j] = v;
            }
        }
    }

    // ==== G5: u1 plane + u2 GEMM (parity 1) + fold dot(Uw3) ====
    __syncthreads();   // all G4 AH reads done before overwrite
    layer1w(S, S.Uw1s, S.Ub1s, tid);
    {
        float acc[64];
        #pragma unroll
        for (int i = 0; i < 64; i++) acc[i] = 0.f;
        fwd256h<1>(gUw2s, acc, smAH, smWH, tid, lane, nq, R0n);
        float pu[2][2] = {{0.f, 0.f}, {0.f, 0.f}};
        #pragma unroll
        for (int sub = 0; sub < 2; sub++) {
            #pragma unroll
            for (int fp = 0; fp < 4; fp++) {
                float* c = acc + (((sub << 2) + fp) << 3);
                #pragma unroll
                for (int h2 = 0; h2 < 2; h2++) {
                    int n = (nq << 6) + (fp << 4) + (h2 << 3) + c2;
                    pu[sub][0] = fmaf(tanhf(c[h2 * 4 + 0] + S.Ub2s[n]), S.Uw3s[n], pu[sub][0]);
                    pu[sub][0] = fmaf(tanhf(c[h2 * 4 + 1] + S.Ub2s[n + 1]), S.Uw3s[n + 1], pu[sub][0]);
                    pu[sub][1] = fmaf(tanhf(c[h2 * 4 + 2] + S.Ub2s[n]), S.Uw3s[n], pu[sub][1]);
                    pu[sub][1] = fmaf(tanhf(c[h2 * 4 + 3] + S.Ub2s[n + 1]), S.Uw3s[n + 1], pu[sub][1]);
                }
            }
            pu[sub][0] += __shfl_xor_sync(0xffffffffu, pu[sub][0], 1);
            pu[sub][0] += __shfl_xor_sync(0xffffffffu, pu[sub][0], 2);
            pu[sub][1] += __shfl_xor_sync(0xffffffffu, pu[sub][1], 1);
            pu[sub][1] += __shfl_xor_sync(0xffffffffu, pu[sub][1], 2);
            if ((lane & 3) == 0) {
                S.Upart[R0n + (sub << 4) + r4][nq] = pu[sub][0];
                S.Upart[R0n + (sub << 4) + r4 + 8][nq] = pu[sub][1];
            }
        }
    }
    __syncthreads();

    // ==== final per-row epilogue ====
    if (tid < CR) {
        int b = tid;
        float V = 0.5f * S.Vpart[b];
        float uu = S.Upart[b][0] + S.Upart[b][1] + S.Upart[b][2] + S.Upart[b][3];
        float u = 20.f * tanhf(uu + Ub3[0]);
        float gv0 = S.Gpart[b][0][0] + S.Gpart[b][1][0] + S.Gpart[b][2][0] + S.Gpart[b][3][0];
        float gv1 = S.Gpart[b][0][1] + S.Gpart[b][1][1] + S.Gpart[b][2][1] + S.Gpart[b][3][1];
        float gv2 = S.Gpart[b][0][2] + S.Gpart[b][1][2] + S.Gpart[b][2][2] + S.Gpart[b][3][2];
        float gv3 = S.Gpart[b][0][3] + S.Gpart[b][1][3] + S.Gpart[b][2][3] + S.Gpart[b][3][3];
        float th = S.X[b][1], v = S.X[b][2], om = S.X[b][3];
        float s, c;
        sincosf(th, &s, &c);
        float den1 = c - 24.7f, den2 = c * c - 24.7f;
        float f2 = (c * (9.8f * s + 11.5f * v) + 68.4f * v - 1.2f * om * om * s) / den1;
        float f3 = (-58.8f * v * c - 243.5f * v - s * (208.3f + om * om * c)) / den2;
        float g2 = (-1.8f * c - 10.9f) / den1;
        float g3 = (9.3f * c + 38.6f) / den2;
        float Lf = gv0 * v + gv1 * om + gv2 * f2 + gv3 * f3;
        float Lg = gv2 * g2 + gv3 * g3;
        int r = base + b;
        out[r] = u;
        out[BSZ + r] = V;
        out[2 * BSZ + r] = Lf + Lg * u;
    }
}

extern "C" void kernel_launch(void* const* d_in, const int* in_sizes, int n_in,
                              void* d_out, int out_size) {
    const float* x   = (const float*)d_in[0];
    const float* Vw1 = (const float*)d_in[1];
    const float* Vb1 = (const float*)d_in[2];
    const float* Vw2 = (const float*)d_in[3];
    const float* Vb2 = (const float*)d_in[4];
    const float* Vw3 = (const float*)d_in[5];
    const float* Vb3 = (const float*)d_in[6];
    const float* Uw1 = (const float*)d_in[7];
    const float* Ub1 = (const float*)d_in[8];
    const float* Uw2 = (const float*)d_in[9];
    const float* Ub2 = (const float*)d_in[10];
    const float* Uw3 = (const float*)d_in[11];
    const float* Ub3 = (const float*)d_in[12];
    float* out = (float*)d_out;

    prep_kernel<<<416, 512>>>(Vw2, Vw3, Uw2);
    cudaFuncSetAttribute(clf_mma, cudaFuncAttributeMaxDynamicSharedMemorySize,
                         (int)sizeof(Smem));
    clf_mma<<<BSZ / CR, NTH, sizeof(Smem)>>>(
        x, Vw1, Vb1, Vb2, Vb3, Uw1, Ub1, Ub2, Uw3, Ub3, out);
}